// round 13
// baseline (speedup 1.0000x reference)
#include <cuda_runtime.h>
#include <cuda_bf16.h>
#include <cstdint>

#define NTOK   2744
#define NPAD   2816           // 22 * 128
#define KSTACK 384
#define BATCH  4
#define CMID   256
#define CIN    1024
#define COUT   1024
#define NHEADS 4
#define DHEAD  64
#define WDIM   14
#define LOG2E  1.44269504f

// ---------------- scratch (static device memory; no allocations) ----------------
__device__ float g_y1 [BATCH*CMID*NTOK];
__device__ float g_qkv[BATCH*3*CMID*NTOK];                 // [b][768][NTOK] (q|k|v)
__device__ float g_rel[NHEADS*DHEAD*NTOK];
__device__ float g_S  [(size_t)BATCH*NHEADS*NTOK*NTOK];    // ~482 MB
__device__ float g_ao [BATCH*CMID*NTOK];
__device__ float g_y3 [BATCH*COUT*NTOK];
__device__ float g_mean[1024];
__device__ float g_istd[1024];
__device__ __nv_bfloat16 g_xa[(size_t)BATCH*NHEADS*NPAD*KSTACK];   // [z][n][384]
__device__ __nv_bfloat16 g_yb[(size_t)BATCH*NHEADS*NPAD*KSTACK];   // [z][m][384]
__device__ __nv_bfloat16 g_vhi[(size_t)BATCH*NHEADS*NPAD*DHEAD];
__device__ __nv_bfloat16 g_vlo[(size_t)BATCH*NHEADS*NPAD*DHEAD];
__device__ float g_rmax [BATCH*NHEADS*NPAD];
// bf16-split GEMM operands
__device__ __nv_bfloat16 g_w1st  [(size_t)CMID*3*CIN];
__device__ __nv_bfloat16 g_wqkvst[(size_t)3*CMID*3*CMID];
__device__ __nv_bfloat16 g_w3st  [(size_t)COUT*3*CMID];
__device__ __nv_bfloat16 g_xst   [(size_t)BATCH*NPAD*3*CIN];
__device__ __nv_bfloat16 g_y1st  [(size_t)BATCH*NPAD*3*CMID];
__device__ __nv_bfloat16 g_aost  [(size_t)BATCH*NPAD*3*CMID];

__device__ __forceinline__ uint32_t smem_u32(const void* p) {
    uint32_t a;
    asm("{ .reg .u64 t; cvta.to.shared.u64 t, %1; cvt.u32.u64 %0, t; }" : "=r"(a) : "l"(p));
    return a;
}
__device__ __forceinline__ void atomicMaxF(float* addr, float val) {
    if (val >= 0.f) atomicMax((int*)addr, __float_as_int(val));
    else            atomicMin((unsigned int*)addr, __float_as_uint(val));
}

// ---------------- rel position tensor ----------------
__global__ void build_rel_kernel(const float* __restrict__ rh,
                                 const float* __restrict__ rw,
                                 const float* __restrict__ rd) {
    int idx = blockIdx.x * 256 + threadIdx.x;
    int n  = idx % NTOK;
    int hd = idx / NTOK;
    int w  = n / (WDIM*WDIM);
    int hh = (n / WDIM) % WDIM;
    int dd = n % WDIM;
    g_rel[idx] = rh[(hd*WDIM + hh)*WDIM + dd]
               + rw[(hd*WDIM + w )*WDIM + dd]
               + rd[(hd*WDIM + w )*WDIM + hh];
}

// ---------------- weight split: W[M][K] -> Wst[M][3K] = [hi|lo|hi] ----------------
__global__ void wsplit(const float* __restrict__ W, __nv_bfloat16* __restrict__ Wst,
                       int total, int K) {
    int idx = blockIdx.x * 256 + threadIdx.x;
    if (idx >= total) return;
    int m = idx / K, k = idx - m*K;
    float v = W[idx];
    __nv_bfloat16 hi = __float2bfloat16(v);
    __nv_bfloat16 lo = __float2bfloat16(v - __bfloat162float(hi));
    size_t base = (size_t)m * 3 * K;
    Wst[base + k]       = hi;
    Wst[base + K + k]   = lo;
    Wst[base + 2*K + k] = hi;
}

// ---------------- activation split+transpose (+optional BN-ReLU) ----------------
__global__ void xsplit(const float* __restrict__ X, __nv_bfloat16* __restrict__ Xst,
                       int C, long strideX, long strideXst,
                       const float* __restrict__ mean, const float* __restrict__ istd,
                       const float* __restrict__ gam, const float* __restrict__ bet) {
    __shared__ float t[32][33];
    const int n0 = blockIdx.x * 32, c0 = blockIdx.y * 32, z = blockIdx.z;
    const int tx = threadIdx.x, ty = threadIdx.y;   // 32 x 8
    #pragma unroll
    for (int r = 0; r < 4; r++) {
        int c = c0 + ty + r*8;
        int n = n0 + tx;
        float v = 0.f;
        if (n < NTOK) {
            v = X[z*strideX + (size_t)c*NTOK + n];
            if (mean) v = fmaxf((v - mean[c]) * istd[c] * gam[c] + bet[c], 0.f);
        }
        t[ty + r*8][tx] = v;
    }
    __syncthreads();
    #pragma unroll
    for (int r = 0; r < 4; r++) {
        int n = n0 + ty + r*8;
        int c = c0 + tx;
        float v = t[tx][ty + r*8];
        __nv_bfloat16 hi = __float2bfloat16(v);
        __nv_bfloat16 lo = __float2bfloat16(v - __bfloat162float(hi));
        size_t base = z*strideXst + (size_t)n * (3*C);
        Xst[base + c]       = hi;
        Xst[base + C + c]   = hi;
        Xst[base + 2*C + c] = lo;
    }
}

// ---------------- generic HMMA GEMM (convs/qkv) ----------------
__global__ __launch_bounds__(256) void gemm_hmma(
    const __nv_bfloat16* __restrict__ A, const __nv_bfloat16* __restrict__ B,
    float* __restrict__ C, int Ks, long strideB, long strideC,
    const float* __restrict__ bias0, const float* __restrict__ bias1,
    const float* __restrict__ bias2)
{
    __shared__ __nv_bfloat16 As[2][128*24];
    __shared__ __nv_bfloat16 Bs[2][128*24];
    const int tid = threadIdx.x;
    const int warp = tid >> 5, lane = tid & 31;
    const int wm = warp >> 2, wn = warp & 3;
    const int z = blockIdx.z;
    const int bm = blockIdx.y * 128, n0 = blockIdx.x * 128;

    const __nv_bfloat16* gA = A + (size_t)(bm + (tid >> 1))*Ks;
    const __nv_bfloat16* gB = B + z*strideB + (size_t)(n0 + (tid >> 1))*Ks;
    const int lrow  = tid >> 1;
    const int lhalf = (tid & 1) * 8;

    const uint32_t sa_base = smem_u32(As);
    const uint32_t sb_base = smem_u32(Bs);
    const int arow = lane & 15, asel = lane >> 4;
    const int brow = lane & 7,  bsel = (lane >> 3) & 1;

    float acc[4][4][4] = {};
    const int steps = Ks >> 4;

    uint4 pa = *(const uint4*)(gA + lhalf);
    uint4 pb = *(const uint4*)(gB + lhalf);

    #pragma unroll 1
    for (int s = 0; s < steps; s++) {
        const int buf = s & 1;
        *(uint4*)&As[buf][lrow*24 + lhalf] = pa;
        *(uint4*)&Bs[buf][lrow*24 + lhalf] = pb;
        __syncthreads();

        if (s + 1 < steps) {
            const int k0 = (s + 1) * 16;
            pa = *(const uint4*)(gA + k0 + lhalf);
            pb = *(const uint4*)(gB + k0 + lhalf);
        }

        uint32_t afr[4][4];
        #pragma unroll
        for (int i = 0; i < 4; i++) {
            const int row = wm*64 + i*16 + arow;
            const uint32_t addr = sa_base + (uint32_t)(buf*128*24 + row*24 + asel*8) * 2;
            asm volatile("ldmatrix.sync.aligned.m8n8.x4.shared.b16 {%0,%1,%2,%3}, [%4];"
                : "=r"(afr[i][0]), "=r"(afr[i][1]), "=r"(afr[i][2]), "=r"(afr[i][3]) : "r"(addr));
        }
        uint32_t bfr[4][2];
        #pragma unroll
        for (int j = 0; j < 4; j++) {
            const int row = wn*32 + j*8 + brow;
            const uint32_t addr = sb_base + (uint32_t)(buf*128*24 + row*24 + bsel*8) * 2;
            asm volatile("ldmatrix.sync.aligned.m8n8.x2.shared.b16 {%0,%1}, [%2];"
                : "=r"(bfr[j][0]), "=r"(bfr[j][1]) : "r"(addr));
        }
        #pragma unroll
        for (int i = 0; i < 4; i++)
            #pragma unroll
            for (int j = 0; j < 4; j++)
                asm volatile(
                    "mma.sync.aligned.m16n8k16.row.col.f32.bf16.bf16.f32 "
                    "{%0,%1,%2,%3}, {%4,%5,%6,%7}, {%8,%9}, {%0,%1,%2,%3};"
                    : "+f"(acc[i][j][0]), "+f"(acc[i][j][1]), "+f"(acc[i][j][2]), "+f"(acc[i][j][3])
                    : "r"(afr[i][0]), "r"(afr[i][1]), "r"(afr[i][2]), "r"(afr[i][3]),
                      "r"(bfr[j][0]), "r"(bfr[j][1]));
    }

    float* Cz = C + z*strideC;
    const int gr = lane >> 2, gc = (lane & 3) * 2;
    #pragma unroll
    for (int i = 0; i < 4; i++) {
        const int r0 = bm + wm*64 + i*16 + gr;
        const int r1 = r0 + 8;
        float bi0 = 0.f, bi1 = 0.f;
        if (bias0) {
            const float* bp0 = (r0 < 256) ? bias0 : (r0 < 512) ? bias1 : bias2;
            const float* bp1 = (r1 < 256) ? bias0 : (r1 < 512) ? bias1 : bias2;
            bi0 = bp0[r0 & 255];
            bi1 = bp1[r1 & 255];
        }
        #pragma unroll
        for (int j = 0; j < 4; j++) {
            const int col = n0 + wn*32 + j*8 + gc;
            if (col < NTOK) {
                *(float2*)&Cz[(size_t)r0*NTOK + col] = make_float2(acc[i][j][0] + bi0, acc[i][j][1] + bi0);
                *(float2*)&Cz[(size_t)r1*NTOK + col] = make_float2(acc[i][j][2] + bi1, acc[i][j][3] + bi1);
            }
        }
    }
}

// ---------------- build bf16-split stacked operands + init g_rmax ----------------
__global__ void build_xy() {
    __shared__ float ta[32][33], tb[32][33];
    const int n0 = blockIdx.x * 32, c0 = blockIdx.y * 32, z = blockIdx.z;
    const int b = z >> 2, h = z & 3;
    const int tx = threadIdx.x, ty = threadIdx.y;    // 32 x 8
    if (blockIdx.y == 0 && ty == 0) g_rmax[z*NPAD + n0 + tx] = -1e30f;
    #pragma unroll
    for (int r = 0; r < 4; r++) {
        int col = c0 + ty + r*8;
        int n = n0 + tx;
        float va = 0.f, vb = 0.f;
        if (n < NTOK) {
            if (col < 64) {
                va = g_qkv[((size_t)b*768 + h*64 + col)*NTOK + n];
                vb = g_qkv[((size_t)b*768 + 256 + h*64 + col)*NTOK + n];
            } else {
                va = g_rel[(size_t)(h*64 + col - 64)*NTOK + n];
                vb = g_qkv[((size_t)b*768 + h*64 + col - 64)*NTOK + n];
            }
        }
        ta[ty + r*8][tx] = va;
        tb[ty + r*8][tx] = vb;
    }
    __syncthreads();
    #pragma unroll
    for (int r = 0; r < 4; r++) {
        int n = n0 + ty + r*8;
        size_t base = ((size_t)z*NPAD + n)*KSTACK;
        int col = c0 + tx;
        float va = ta[tx][ty + r*8];
        float vb = tb[tx][ty + r*8];
        __nv_bfloat16 ha = __float2bfloat16(va);
        __nv_bfloat16 la = __float2bfloat16(va - __bfloat162float(ha));
        __nv_bfloat16 hb = __float2bfloat16(vb);
        __nv_bfloat16 lb = __float2bfloat16(vb - __bfloat162float(hb));
        g_xa[base + col]       = ha;
        g_xa[base + 128 + col] = la;
        g_xa[base + 256 + col] = ha;
        g_yb[base + col]       = hb;
        g_yb[base + 128 + col] = hb;
        g_yb[base + 256 + col] = lb;
    }
}

// ---------------- V split ----------------
__global__ void vsplit() {
    __shared__ float t[32][33];
    const int m0 = blockIdx.x * 32, c0 = blockIdx.y * 32, z = blockIdx.z;
    const int b = z >> 2, h = z & 3;
    const int tx = threadIdx.x, ty = threadIdx.y;   // 32 x 8
    #pragma unroll
    for (int r = 0; r < 4; r++) {
        int c = c0 + ty + r*8;
        int m = m0 + tx;
        t[ty + r*8][tx] = (m < NTOK) ? g_qkv[((size_t)b*768 + 512 + h*64 + c)*NTOK + m] : 0.f;
    }
    __syncthreads();
    #pragma unroll
    for (int r = 0; r < 4; r++) {
        int m = m0 + ty + r*8;
        float v = t[tx][ty + r*8];
        __nv_bfloat16 hi = __float2bfloat16(v);
        __nv_bfloat16 lo = __float2bfloat16(v - __bfloat162float(hi));
        size_t idx = ((size_t)z*NPAD + m)*DHEAD + c0 + tx;
        g_vhi[idx] = hi;
        g_vlo[idx] = lo;
    }
}

// ---------------- HMMA S-tile kernel (128n x 256m CTA tile, 64x64 warp tile) + row-max atomics ----------------
__global__ __launch_bounds__(256) void tn_s_mma() {
    __shared__ __nv_bfloat16 As[2][128*24];
    __shared__ __nv_bfloat16 Bs[2][256*24];
    const int tid = threadIdx.x;
    const int warp = tid >> 5, lane = tid & 31;
    const int wn = warp >> 2;        // 0..1 : n-dim 64 rows
    const int wm = warp & 3;         // 0..3 : m-dim 64 cols
    const int z = blockIdx.z;
    const int n0 = blockIdx.y * 128, m0 = blockIdx.x * 256;

    const __nv_bfloat16* xa = g_xa + ((size_t)z*NPAD + n0)*KSTACK;
    const __nv_bfloat16* yb = g_yb + ((size_t)z*NPAD + m0)*KSTACK;

    const int larow  = tid >> 1;
    const int lahalf = (tid & 1) * 8;
    const __nv_bfloat16* gA = xa + (size_t)larow*KSTACK + lahalf;
    const __nv_bfloat16* gB = yb + (size_t)tid*KSTACK;

    const uint32_t sa_base = smem_u32(As);
    const uint32_t sb_base = smem_u32(Bs);

    float acc[4][8][4] = {};   // [n m16 tile][m n8 tile][frag]

    uint4 pa  = *(const uint4*)(gA);
    uint4 pb0 = *(const uint4*)(gB);
    uint4 pb1 = *(const uint4*)(gB + 8);

    #pragma unroll 1
    for (int s = 0; s < 24; s++) {
        const int buf = s & 1;
        *(uint4*)&As[buf][larow*24 + lahalf] = pa;
        *(uint4*)&Bs[buf][tid*24]     = pb0;
        *(uint4*)&Bs[buf][tid*24 + 8] = pb1;
        __syncthreads();

        if (s + 1 < 24) {
            const int k0 = (s + 1) * 16;
            pa  = *(const uint4*)(gA + k0);
            pb0 = *(const uint4*)(gB + k0);
            pb1 = *(const uint4*)(gB + k0 + 8);
        }

        uint32_t afr[4][4];
        #pragma unroll
        for (int i = 0; i < 4; i++) {
            const int row = wn*64 + i*16 + (lane & 15);
            const uint32_t addr = sa_base + (uint32_t)(buf*128*24 + row*24 + (lane >> 4)*8) * 2;
            asm volatile("ldmatrix.sync.aligned.m8n8.x4.shared.b16 {%0,%1,%2,%3}, [%4];"
                : "=r"(afr[i][0]), "=r"(afr[i][1]), "=r"(afr[i][2]), "=r"(afr[i][3]) : "r"(addr));
        }
        uint32_t bfr[4][4];   // x4 matrices: r0=(n0-7,k0-7) r1=(n8-15,k0-7) r2=(n0-7,k8-15) r3=(n8-15,k8-15)
        #pragma unroll
        for (int jp = 0; jp < 4; jp++) {
            const int row = wm*64 + jp*16 + (lane & 15);
            const uint32_t addr = sb_base + (uint32_t)(buf*256*24 + row*24 + (lane >> 4)*8) * 2;
            asm volatile("ldmatrix.sync.aligned.m8n8.x4.shared.b16 {%0,%1,%2,%3}, [%4];"
                : "=r"(bfr[jp][0]), "=r"(bfr[jp][1]), "=r"(bfr[jp][2]), "=r"(bfr[jp][3]) : "r"(addr));
        }
        #pragma unroll
        for (int i = 0; i < 4; i++)
            #pragma unroll
            for (int jp = 0; jp < 4; jp++) {
                // first n8 block: k-halves (r0, r2); second n8 block: (r1, r3)
                asm volatile(
                    "mma.sync.aligned.m16n8k16.row.col.f32.bf16.bf16.f32 "
                    "{%0,%1,%2,%3}, {%4,%5,%6,%7}, {%8,%9}, {%0,%1,%2,%3};"
                    : "+f"(acc[i][2*jp][0]), "+f"(acc[i][2*jp][1]), "+f"(acc[i][2*jp][2]), "+f"(acc[i][2*jp][3])
                    : "r"(afr[i][0]), "r"(afr[i][1]), "r"(afr[i][2]), "r"(afr[i][3]),
                      "r"(bfr[jp][0]), "r"(bfr[jp][2]));
                asm volatile(
                    "mma.sync.aligned.m16n8k16.row.col.f32.bf16.bf16.f32 "
                    "{%0,%1,%2,%3}, {%4,%5,%6,%7}, {%8,%9}, {%0,%1,%2,%3};"
                    : "+f"(acc[i][2*jp+1][0]), "+f"(acc[i][2*jp+1][1]), "+f"(acc[i][2*jp+1][2]), "+f"(acc[i][2*jp+1][3])
                    : "r"(afr[i][0]), "r"(afr[i][1]), "r"(afr[i][2]), "r"(afr[i][3]),
                      "r"(bfr[jp][1]), "r"(bfr[jp][3]));
            }
    }

    float* C = g_S + (size_t)z*NTOK*NTOK;
    const int gr = lane >> 2, gc = (lane & 3) * 2;
    #pragma unroll
    for (int i = 0; i < 4; i++) {
        const int r0 = n0 + wn*64 + i*16 + gr;
        const int r1 = r0 + 8;
        float mr0 = -1e30f, mr1 = -1e30f;
        #pragma unroll
        for (int j = 0; j < 8; j++) {
            const int col = m0 + wm*64 + j*8 + gc;
            if (col < NTOK) {
                mr0 = fmaxf(mr0, acc[i][j][0]);
                mr1 = fmaxf(mr1, acc[i][j][2]);
                if (r0 < NTOK) *(float2*)&C[(size_t)r0*NTOK + col] = make_float2(acc[i][j][0], acc[i][j][1]);
                if (r1 < NTOK) *(float2*)&C[(size_t)r1*NTOK + col] = make_float2(acc[i][j][2], acc[i][j][3]);
            }
            if (col + 1 < NTOK) {
                mr0 = fmaxf(mr0, acc[i][j][1]);
                mr1 = fmaxf(mr1, acc[i][j][3]);
            }
        }
        mr0 = fmaxf(mr0, __shfl_xor_sync(0xffffffffu, mr0, 1));
        mr0 = fmaxf(mr0, __shfl_xor_sync(0xffffffffu, mr0, 2));
        mr1 = fmaxf(mr1, __shfl_xor_sync(0xffffffffu, mr1, 1));
        mr1 = fmaxf(mr1, __shfl_xor_sync(0xffffffffu, mr1, 2));
        if ((lane & 3) == 0) {
            if (r0 < NTOK) atomicMaxF(&g_rmax[z*NPAD + r0], mr0);
            if (r1 < NTOK) atomicMaxF(&g_rmax[z*NPAD + r1], mr1);
        }
    }
}

// ---------------- HMMA AV kernel: inline exp + inline row-sum, divide at end ----------------
__global__ __launch_bounds__(256) void av_mma() {
    extern __shared__ __nv_bfloat16 dsm[];
    __nv_bfloat16* Ahi = dsm;
    __nv_bfloat16* Alo = Ahi + 128*72;
    __nv_bfloat16* Bhi = Alo + 128*72;
    __nv_bfloat16* Blo = Bhi + 64*72;
    __shared__ float Ls[128][2];

    const int tid = threadIdx.x;
    const int warp = tid >> 5, lane = tid & 31;
    const int wn = warp >> 1, wd = warp & 1;
    const int z = blockIdx.y, b = z >> 2, h = z & 3;
    const int n0 = blockIdx.x * 128;

    const int lr = tid >> 1;
    const int lch = (tid & 1) * 32;
    const int n_ld = n0 + lr;
    const bool rowok = n_ld < NTOK;
    const float mx = rowok ? g_rmax[z*NPAD + n_ld] : 0.f;
    const float* Srow = g_S + (size_t)z*NTOK*NTOK + (size_t)n_ld*NTOK;

    const uint32_t sa_hi = smem_u32(Ahi);
    const uint32_t sa_lo = smem_u32(Alo);
    const uint32_t sb_hi = smem_u32(Bhi);
    const uint32_t sb_lo = smem_u32(Blo);

    float acc[2][4][4] = {};
    float lsum = 0.f;

    for (int ch = 0; ch < 43; ch++) {
        const int mc = ch * 64;
        __syncthreads();

        #pragma unroll
        for (int i = 0; i < 8; i++) {
            const int m = mc + lch + i*4;
            float4 pv = make_float4(0.f,0.f,0.f,0.f);
            if (rowok && m < NTOK) {
                float4 s = *(const float4*)(Srow + m);
                pv.x = exp2f((s.x - mx) * LOG2E);
                pv.y = exp2f((s.y - mx) * LOG2E);
                pv.z = exp2f((s.z - mx) * LOG2E);
                pv.w = exp2f((s.w - mx) * LOG2E);
                lsum += pv.x + pv.y + pv.z + pv.w;
            }
            __nv_bfloat162 h01 = __floats2bfloat162_rn(pv.x, pv.y);
            __nv_bfloat162 h23 = __floats2bfloat162_rn(pv.z, pv.w);
            __nv_bfloat162 l01 = __floats2bfloat162_rn(pv.x - __bfloat162float(__low2bfloat16(h01)),
                                                       pv.y - __bfloat162float(__high2bfloat16(h01)));
            __nv_bfloat162 l23 = __floats2bfloat162_rn(pv.z - __bfloat162float(__low2bfloat16(h23)),
                                                       pv.w - __bfloat162float(__high2bfloat16(h23)));
            const int o = lr*72 + lch + i*4;
            *(__nv_bfloat162*)(Ahi + o)     = h01;
            *(__nv_bfloat162*)(Ahi + o + 2) = h23;
            *(__nv_bfloat162*)(Alo + o)     = l01;
            *(__nv_bfloat162*)(Alo + o + 2) = l23;
        }
        #pragma unroll
        for (int i = 0; i < 2; i++) {
            const int idx = tid + 256*i;
            const int row = idx >> 3, seg = (idx & 7) * 8;
            const size_t gsrc = ((size_t)z*NPAD + mc + row)*DHEAD + seg;
            *(uint4*)(Bhi + row*72 + seg) = *(const uint4*)(g_vhi + gsrc);
            *(uint4*)(Blo + row*72 + seg) = *(const uint4*)(g_vlo + gsrc);
        }
        __syncthreads();

        #pragma unroll
        for (int step = 0; step < 4; step++) {
            const int k0 = step * 16;
            uint32_t ah[2][4], al[2][4];
            #pragma unroll
            for (int i = 0; i < 2; i++) {
                const uint32_t off = (uint32_t)((wn*32 + i*16 + (lane & 15))*72 + k0 + ((lane >> 4) << 3)) * 2;
                asm volatile("ldmatrix.sync.aligned.m8n8.x4.shared.b16 {%0,%1,%2,%3}, [%4];"
                    : "=r"(ah[i][0]), "=r"(ah[i][1]), "=r"(ah[i][2]), "=r"(ah[i][3]) : "r"(sa_hi + off));
                asm volatile("ldmatrix.sync.aligned.m8n8.x4.shared.b16 {%0,%1,%2,%3}, [%4];"
                    : "=r"(al[i][0]), "=r"(al[i][1]), "=r"(al[i][2]), "=r"(al[i][3]) : "r"(sa_lo + off));
            }
            uint32_t bh[2][4], bl[2][4];
            #pragma unroll
            for (int jj = 0; jj < 2; jj++) {
                const int d0 = wd*32 + jj*16;
                const uint32_t off = (uint32_t)((k0 + (lane & 7) + ((lane >> 3) & 1)*8)*72 + d0 + ((lane >> 4) << 3)) * 2;
                asm volatile("ldmatrix.sync.aligned.m8n8.x4.trans.shared.b16 {%0,%1,%2,%3}, [%4];"
                    : "=r"(bh[jj][0]), "=r"(bh[jj][1]), "=r"(bh[jj][2]), "=r"(bh[jj][3]) : "r"(sb_hi + off));
                asm volatile("ldmatrix.sync.aligned.m8n8.x4.trans.shared.b16 {%0,%1,%2,%3}, [%4];"
                    : "=r"(bl[jj][0]), "=r"(bl[jj][1]), "=r"(bl[jj][2]), "=r"(bl[jj][3]) : "r"(sb_lo + off));
            }
            #define AV_MMA(ac, af, b0, b1) \
                asm volatile("mma.sync.aligned.m16n8k16.row.col.f32.bf16.bf16.f32 " \
                    "{%0,%1,%2,%3}, {%4,%5,%6,%7}, {%8,%9}, {%0,%1,%2,%3};" \
                    : "+f"((ac)[0]), "+f"((ac)[1]), "+f"((ac)[2]), "+f"((ac)[3]) \
                    : "r"((af)[0]), "r"((af)[1]), "r"((af)[2]), "r"((af)[3]), "r"(b0), "r"(b1))
            #pragma unroll
            for (int i = 0; i < 2; i++)
                #pragma unroll
                for (int jj = 0; jj < 2; jj++) {
                    AV_MMA(acc[i][jj*2+0], ah[i], bh[jj][0], bh[jj][1]);
                    AV_MMA(acc[i][jj*2+1], ah[i], bh[jj][2], bh[jj][3]);
                    AV_MMA(acc[i][jj*2+0], al[i], bh[jj][0], bh[jj][1]);
                    AV_MMA(acc[i][jj*2+1], al[i], bh[jj][2], bh[jj][3]);
                    AV_MMA(acc[i][jj*2+0], ah[i], bl[jj][0], bl[jj][1]);
                    AV_MMA(acc[i][jj*2+1], ah[i], bl[jj][2], bl[jj][3]);
                }
            #undef AV_MMA
        }
    }

    Ls[lr][tid & 1] = lsum;
    __syncthreads();

    const int baseCh = b*CMID + h*DHEAD;
    const int gr = lane >> 2, gc = (lane & 3) * 2;
    #pragma unroll
    for (int i = 0; i < 2; i++) {
        const int lr0 = wn*32 + i*16 + gr;
        const int lr1 = lr0 + 8;
        const int r0 = n0 + lr0;
        const int r1 = n0 + lr1;
        const float inv0 = 1.f / (Ls[lr0][0] + Ls[lr0][1]);
        const float inv1 = 1.f / (Ls[lr1][0] + Ls[lr1][1]);
        #pragma unroll
        for (int j = 0; j < 4; j++) {
            const int d = wd*32 + j*8 + gc;
            float* c0p = g_ao + (size_t)(baseCh + d)*NTOK;
            float* c1p = g_ao + (size_t)(baseCh + d + 1)*NTOK;
            if (r0 < NTOK) { c0p[r0] = acc[i][j][0]*inv0; c1p[r0] = acc[i][j][1]*inv0; }
            if (r1 < NTOK) { c0p[r1] = acc[i][j][2]*inv1; c1p[r1] = acc[i][j][3]*inv1; }
        }
    }
}

// ---------------- BatchNorm ----------------
__global__ __launch_bounds__(256) void bn_stats(const float* __restrict__ x, int C,
                                                float* __restrict__ mean, float* __restrict__ istd) {
    const int c = blockIdx.x;
    const int tid = threadIdx.x;
    const int lane = tid & 31, wid = tid >> 5;
    float s = 0.f, sq = 0.f;
    for (int i = tid; i < BATCH*NTOK; i += 256) {
        int b = i / NTOK, n = i - b*NTOK;
        float v = x[((long)b*C + c)*NTOK + n];
        s += v; sq += v*v;
    }
    #pragma unroll
    for (int d = 16; d > 0; d >>= 1) {
        s  += __shfl_xor_sync(0xffffffffu, s, d);
        sq += __shfl_xor_sync(0xffffffffu, sq, d);
    }
    __shared__ float r1[8], r2[8];
    if (lane == 0) { r1[wid] = s; r2[wid] = sq; }
    __syncthreads();
    if (tid == 0) {
        float S1 = 0.f, S2 = 0.f;
        #pragma unroll
        for (int w = 0; w < 8; w++) { S1 += r1[w]; S2 += r2[w]; }
        const float inv_cnt = 1.f / (BATCH*NTOK);
        float m = S1 * inv_cnt;
        float var = S2 * inv_cnt - m*m;
        mean[c] = m;
        istd[c] = rsqrtf(var + 1e-5f);
    }
}

__global__ void bn_res_relu(const float* __restrict__ y, const float* __restrict__ xres,
                            float* __restrict__ out,
                            const float* __restrict__ mean, const float* __restrict__ istd,
                            const float* __restrict__ g, const float* __restrict__ bp) {
    long idx = (long)blockIdx.x * 256 + threadIdx.x;
    if (idx >= (long)BATCH*COUT*NTOK) return;
    int c = (int)((idx / NTOK) % COUT);
    float v = (y[idx] - mean[c]) * istd[c] * g[c] + bp[c] + xres[idx];
    out[idx] = fmaxf(v, 0.f);
}

// ---------------- launch ----------------
extern "C" void kernel_launch(void* const* d_in, const int* in_sizes, int n_in,
                              void* d_out, int out_size) {
    const float* x    = (const float*)d_in[0];
    const float* W1   = (const float*)d_in[1];
    const float* g1   = (const float*)d_in[2];
    const float* b1   = (const float*)d_in[3];
    const float* Wq   = (const float*)d_in[4];
    const float* bq   = (const float*)d_in[5];
    const float* Wk   = (const float*)d_in[6];
    const float* bk   = (const float*)d_in[7];
    const float* Wv   = (const float*)d_in[8];
    const float* bv   = (const float*)d_in[9];
    const float* relh = (const float*)d_in[10];
    const float* relw = (const float*)d_in[11];
    const float* reld = (const float*)d_in[12];
    const float* g2   = (const float*)d_in[13];
    const float* b2   = (const float*)d_in[14];
    const float* W3   = (const float*)d_in[15];
    const float* g3   = (const float*)d_in[16];
    const float* b3   = (const float*)d_in[17];
    float* out = (float*)d_out;

    float *y1, *ao, *y3, *mean, *istd, *qkv;
    __nv_bfloat16 *w1st, *wqkvst, *w3st, *xst, *y1st, *aost;
    cudaGetSymbolAddress((void**)&y1,  g_y1);
    cudaGetSymbolAddress((void**)&ao,  g_ao);
    cudaGetSymbolAddress((void**)&y3,  g_y3);
    cudaGetSymbolAddress((void**)&mean,g_mean);
    cudaGetSymbolAddress((void**)&istd,g_istd);
    cudaGetSymbolAddress((void**)&qkv, g_qkv);
    cudaGetSymbolAddress((void**)&w1st,  g_w1st);
    cudaGetSymbolAddress((void**)&wqkvst,g_wqkvst);
    cudaGetSymbolAddress((void**)&w3st,  g_w3st);
    cudaGetSymbolAddress((void**)&xst,   g_xst);
    cudaGetSymbolAddress((void**)&y1st,  g_y1st);
    cudaGetSymbolAddress((void**)&aost,  g_aost);

    const dim3 blk(256);
    const int NT = (NTOK + 127) / 128;        // 22
    const int NT32 = NPAD / 32;               // 88
    const int AV_SMEM = (2*128*72 + 2*64*72) * 2;
    cudaFuncSetAttribute(av_mma, cudaFuncAttributeMaxDynamicSharedMemorySize, AV_SMEM);

    // weight splits
    wsplit<<<(CMID*CIN + 255)/256, blk>>>(W1, w1st, CMID*CIN, CIN);
    wsplit<<<(CMID*CMID + 255)/256, blk>>>(Wq, wqkvst,                    CMID*CMID, CMID);
    wsplit<<<(CMID*CMID + 255)/256, blk>>>(Wk, wqkvst + (size_t)256*768,  CMID*CMID, CMID);
    wsplit<<<(CMID*CMID + 255)/256, blk>>>(Wv, wqkvst + (size_t)512*768,  CMID*CMID, CMID);
    wsplit<<<(COUT*CMID + 255)/256, blk>>>(W3, w3st, COUT*CMID, CMID);

    // x split -> conv1 (HMMA)
    xsplit<<<dim3(NT32, CIN/32, BATCH), dim3(32,8)>>>(x, xst, CIN,
        (long)CIN*NTOK, (long)NPAD*3*CIN, nullptr, nullptr, nullptr, nullptr);
    gemm_hmma<<<dim3(NT, 2, BATCH), blk>>>(w1st, xst, y1, 3*CIN,
        (long)NPAD*3*CIN, (long)CMID*NTOK, nullptr, nullptr, nullptr);
    bn_stats<<<CMID, 256>>>(y1, CMID, mean, istd);

    // BN1+ReLU fused into split -> qkv (HMMA, stacked M=768)
    xsplit<<<dim3(NT32, CMID/32, BATCH), dim3(32,8)>>>(y1, y1st, CMID,
        (long)CMID*NTOK, (long)NPAD*3*CMID, mean, istd, g1, b1);
    gemm_hmma<<<dim3(NT, 6, BATCH), blk>>>(wqkvst, y1st, qkv, 3*CMID,
        (long)NPAD*3*CMID, (long)768*NTOK, bq, bk, bv);

    // rel tensor + attention operand prep (build_xy also inits g_rmax)
    build_rel_kernel<<<(NHEADS*DHEAD*NTOK)/256, 256>>>(relh, relw, reld);
    build_xy<<<dim3(NT32, 4, BATCH*NHEADS), dim3(32,8)>>>();
    vsplit<<<dim3(NT32, 2, BATCH*NHEADS), dim3(32,8)>>>();

    // attention: logits+rowmax (HMMA, 128x256 tiles) -> AV (HMMA, softmax+rowsum inline)
    tn_s_mma<<<dim3(NPAD/256, NT, BATCH*NHEADS), blk>>>();
    av_mma<<<dim3(NT, BATCH*NHEADS), blk, AV_SMEM>>>();

    // BN2+ReLU fused into split -> conv3 (HMMA)
    bn_stats<<<CMID, 256>>>(ao, CMID, mean, istd);
    xsplit<<<dim3(NT32, CMID/32, BATCH), dim3(32,8)>>>(ao, aost, CMID,
        (long)CMID*NTOK, (long)NPAD*3*CMID, mean, istd, g2, b2);
    gemm_hmma<<<dim3(NT, 8, BATCH), blk>>>(w3st, aost, y3, 3*CMID,
        (long)NPAD*3*CMID, (long)COUT*NTOK, nullptr, nullptr, nullptr);

    // BN3 + residual + ReLU
    bn_stats<<<COUT, 256>>>(y3, COUT, mean, istd);
    bn_res_relu<<<(BATCH*COUT*NTOK)/256, 256>>>(y3, x, out, mean, istd, g3, b3);
}

// round 14
// speedup vs baseline: 1.0456x; 1.0456x over previous
#include <cuda_runtime.h>
#include <cuda_bf16.h>
#include <cstdint>

#define NTOK   2744
#define NPAD   2816           // 22 * 128
#define KSTACK 384
#define BATCH  4
#define CMID   256
#define CIN    1024
#define COUT   1024
#define NHEADS 4
#define DHEAD  64
#define WDIM   14
#define LOG2E  1.44269504f

// ---------------- scratch (static device memory; no allocations) ----------------
__device__ float g_y1 [BATCH*CMID*NTOK];
__device__ float g_qkv[BATCH*3*CMID*NTOK];                 // [b][768][NTOK] (q|k|v)
__device__ float g_rel[NHEADS*DHEAD*NTOK];
__device__ float g_S  [(size_t)BATCH*NHEADS*NTOK*NTOK];    // ~482 MB
__device__ float g_ao [BATCH*CMID*NTOK];
__device__ float g_y3 [BATCH*COUT*NTOK];
__device__ float g_mean[1024];
__device__ float g_istd[1024];
__device__ __nv_bfloat16 g_xa[(size_t)BATCH*NHEADS*NPAD*KSTACK];   // [z][n][384]
__device__ __nv_bfloat16 g_yb[(size_t)BATCH*NHEADS*NPAD*KSTACK];   // [z][m][384]
__device__ __nv_bfloat16 g_vhi[(size_t)BATCH*NHEADS*NPAD*DHEAD];
__device__ __nv_bfloat16 g_vlo[(size_t)BATCH*NHEADS*NPAD*DHEAD];
__device__ float g_rmax [BATCH*NHEADS*NPAD];
// bf16-split GEMM operands
__device__ __nv_bfloat16 g_w1st  [(size_t)CMID*3*CIN];
__device__ __nv_bfloat16 g_wqkvst[(size_t)3*CMID*3*CMID];
__device__ __nv_bfloat16 g_w3st  [(size_t)COUT*3*CMID];
__device__ __nv_bfloat16 g_xst   [(size_t)BATCH*NPAD*3*CIN];
__device__ __nv_bfloat16 g_y1st  [(size_t)BATCH*NPAD*3*CMID];
__device__ __nv_bfloat16 g_aost  [(size_t)BATCH*NPAD*3*CMID];

__device__ __forceinline__ uint32_t smem_u32(const void* p) {
    uint32_t a;
    asm("{ .reg .u64 t; cvta.to.shared.u64 t, %1; cvt.u32.u64 %0, t; }" : "=r"(a) : "l"(p));
    return a;
}
__device__ __forceinline__ void atomicMaxF(float* addr, float val) {
    if (val >= 0.f) atomicMax((int*)addr, __float_as_int(val));
    else            atomicMin((unsigned int*)addr, __float_as_uint(val));
}

// ---------------- rel position tensor ----------------
__global__ void build_rel_kernel(const float* __restrict__ rh,
                                 const float* __restrict__ rw,
                                 const float* __restrict__ rd) {
    int idx = blockIdx.x * 256 + threadIdx.x;
    int n  = idx % NTOK;
    int hd = idx / NTOK;
    int w  = n / (WDIM*WDIM);
    int hh = (n / WDIM) % WDIM;
    int dd = n % WDIM;
    g_rel[idx] = rh[(hd*WDIM + hh)*WDIM + dd]
               + rw[(hd*WDIM + w )*WDIM + dd]
               + rd[(hd*WDIM + w )*WDIM + hh];
}

// ---------------- weight split: W[M][K] -> Wst[M][3K] = [hi|lo|hi] ----------------
__global__ void wsplit(const float* __restrict__ W, __nv_bfloat16* __restrict__ Wst,
                       int total, int K) {
    int idx = blockIdx.x * 256 + threadIdx.x;
    if (idx >= total) return;
    int m = idx / K, k = idx - m*K;
    float v = W[idx];
    __nv_bfloat16 hi = __float2bfloat16(v);
    __nv_bfloat16 lo = __float2bfloat16(v - __bfloat162float(hi));
    size_t base = (size_t)m * 3 * K;
    Wst[base + k]       = hi;
    Wst[base + K + k]   = lo;
    Wst[base + 2*K + k] = hi;
}

// ---------------- activation split+transpose (+optional BN-ReLU) ----------------
__global__ void xsplit(const float* __restrict__ X, __nv_bfloat16* __restrict__ Xst,
                       int C, long strideX, long strideXst,
                       const float* __restrict__ mean, const float* __restrict__ istd,
                       const float* __restrict__ gam, const float* __restrict__ bet) {
    __shared__ float t[32][33];
    const int n0 = blockIdx.x * 32, c0 = blockIdx.y * 32, z = blockIdx.z;
    const int tx = threadIdx.x, ty = threadIdx.y;   // 32 x 8
    #pragma unroll
    for (int r = 0; r < 4; r++) {
        int c = c0 + ty + r*8;
        int n = n0 + tx;
        float v = 0.f;
        if (n < NTOK) {
            v = X[z*strideX + (size_t)c*NTOK + n];
            if (mean) v = fmaxf((v - mean[c]) * istd[c] * gam[c] + bet[c], 0.f);
        }
        t[ty + r*8][tx] = v;
    }
    __syncthreads();
    #pragma unroll
    for (int r = 0; r < 4; r++) {
        int n = n0 + ty + r*8;
        int c = c0 + tx;
        float v = t[tx][ty + r*8];
        __nv_bfloat16 hi = __float2bfloat16(v);
        __nv_bfloat16 lo = __float2bfloat16(v - __bfloat162float(hi));
        size_t base = z*strideXst + (size_t)n * (3*C);
        Xst[base + c]       = hi;
        Xst[base + C + c]   = hi;
        Xst[base + 2*C + c] = lo;
    }
}

// ---------------- generic HMMA GEMM (convs/qkv), B via x4 ldmatrix ----------------
__global__ __launch_bounds__(256) void gemm_hmma(
    const __nv_bfloat16* __restrict__ A, const __nv_bfloat16* __restrict__ B,
    float* __restrict__ C, int Ks, long strideB, long strideC,
    const float* __restrict__ bias0, const float* __restrict__ bias1,
    const float* __restrict__ bias2)
{
    __shared__ __nv_bfloat16 As[2][128*24];
    __shared__ __nv_bfloat16 Bs[2][128*24];
    const int tid = threadIdx.x;
    const int warp = tid >> 5, lane = tid & 31;
    const int wm = warp >> 2, wn = warp & 3;
    const int z = blockIdx.z;
    const int bm = blockIdx.y * 128, n0 = blockIdx.x * 128;

    const __nv_bfloat16* gA = A + (size_t)(bm + (tid >> 1))*Ks;
    const __nv_bfloat16* gB = B + z*strideB + (size_t)(n0 + (tid >> 1))*Ks;
    const int lrow  = tid >> 1;
    const int lhalf = (tid & 1) * 8;

    const uint32_t sa_base = smem_u32(As);
    const uint32_t sb_base = smem_u32(Bs);

    float acc[4][4][4] = {};
    const int steps = Ks >> 4;

    uint4 pa = *(const uint4*)(gA + lhalf);
    uint4 pb = *(const uint4*)(gB + lhalf);

    #pragma unroll 1
    for (int s = 0; s < steps; s++) {
        const int buf = s & 1;
        *(uint4*)&As[buf][lrow*24 + lhalf] = pa;
        *(uint4*)&Bs[buf][lrow*24 + lhalf] = pb;
        __syncthreads();

        if (s + 1 < steps) {
            const int k0 = (s + 1) * 16;
            pa = *(const uint4*)(gA + k0 + lhalf);
            pb = *(const uint4*)(gB + k0 + lhalf);
        }

        uint32_t afr[4][4];
        #pragma unroll
        for (int i = 0; i < 4; i++) {
            const int row = wm*64 + i*16 + (lane & 15);
            const uint32_t addr = sa_base + (uint32_t)(buf*128*24 + row*24 + (lane >> 4)*8) * 2;
            asm volatile("ldmatrix.sync.aligned.m8n8.x4.shared.b16 {%0,%1,%2,%3}, [%4];"
                : "=r"(afr[i][0]), "=r"(afr[i][1]), "=r"(afr[i][2]), "=r"(afr[i][3]) : "r"(addr));
        }
        // B via 2 x4 loads: matrices r0=(n0-7,k0-7) r1=(n8-15,k0-7) r2=(n0-7,k8-15) r3=(n8-15,k8-15)
        uint32_t bfr[2][4];
        #pragma unroll
        for (int jp = 0; jp < 2; jp++) {
            const int row = wn*32 + jp*16 + (lane & 15);
            const uint32_t addr = sb_base + (uint32_t)(buf*128*24 + row*24 + (lane >> 4)*8) * 2;
            asm volatile("ldmatrix.sync.aligned.m8n8.x4.shared.b16 {%0,%1,%2,%3}, [%4];"
                : "=r"(bfr[jp][0]), "=r"(bfr[jp][1]), "=r"(bfr[jp][2]), "=r"(bfr[jp][3]) : "r"(addr));
        }
        #pragma unroll
        for (int i = 0; i < 4; i++)
            #pragma unroll
            for (int jp = 0; jp < 2; jp++) {
                asm volatile(
                    "mma.sync.aligned.m16n8k16.row.col.f32.bf16.bf16.f32 "
                    "{%0,%1,%2,%3}, {%4,%5,%6,%7}, {%8,%9}, {%0,%1,%2,%3};"
                    : "+f"(acc[i][2*jp][0]), "+f"(acc[i][2*jp][1]), "+f"(acc[i][2*jp][2]), "+f"(acc[i][2*jp][3])
                    : "r"(afr[i][0]), "r"(afr[i][1]), "r"(afr[i][2]), "r"(afr[i][3]),
                      "r"(bfr[jp][0]), "r"(bfr[jp][2]));
                asm volatile(
                    "mma.sync.aligned.m16n8k16.row.col.f32.bf16.bf16.f32 "
                    "{%0,%1,%2,%3}, {%4,%5,%6,%7}, {%8,%9}, {%0,%1,%2,%3};"
                    : "+f"(acc[i][2*jp+1][0]), "+f"(acc[i][2*jp+1][1]), "+f"(acc[i][2*jp+1][2]), "+f"(acc[i][2*jp+1][3])
                    : "r"(afr[i][0]), "r"(afr[i][1]), "r"(afr[i][2]), "r"(afr[i][3]),
                      "r"(bfr[jp][1]), "r"(bfr[jp][3]));
            }
    }

    float* Cz = C + z*strideC;
    const int gr = lane >> 2, gc = (lane & 3) * 2;
    #pragma unroll
    for (int i = 0; i < 4; i++) {
        const int r0 = bm + wm*64 + i*16 + gr;
        const int r1 = r0 + 8;
        float bi0 = 0.f, bi1 = 0.f;
        if (bias0) {
            const float* bp0 = (r0 < 256) ? bias0 : (r0 < 512) ? bias1 : bias2;
            const float* bp1 = (r1 < 256) ? bias0 : (r1 < 512) ? bias1 : bias2;
            bi0 = bp0[r0 & 255];
            bi1 = bp1[r1 & 255];
        }
        #pragma unroll
        for (int j = 0; j < 4; j++) {
            const int col = n0 + wn*32 + j*8 + gc;
            if (col < NTOK) {
                *(float2*)&Cz[(size_t)r0*NTOK + col] = make_float2(acc[i][j][0] + bi0, acc[i][j][1] + bi0);
                *(float2*)&Cz[(size_t)r1*NTOK + col] = make_float2(acc[i][j][2] + bi1, acc[i][j][3] + bi1);
            }
        }
    }
}

// ---------------- build bf16-split stacked operands + init g_rmax ----------------
__global__ void build_xy() {
    __shared__ float ta[32][33], tb[32][33];
    const int n0 = blockIdx.x * 32, c0 = blockIdx.y * 32, z = blockIdx.z;
    const int b = z >> 2, h = z & 3;
    const int tx = threadIdx.x, ty = threadIdx.y;    // 32 x 8
    if (blockIdx.y == 0 && ty == 0) g_rmax[z*NPAD + n0 + tx] = -1e30f;
    #pragma unroll
    for (int r = 0; r < 4; r++) {
        int col = c0 + ty + r*8;
        int n = n0 + tx;
        float va = 0.f, vb = 0.f;
        if (n < NTOK) {
            if (col < 64) {
                va = g_qkv[((size_t)b*768 + h*64 + col)*NTOK + n];
                vb = g_qkv[((size_t)b*768 + 256 + h*64 + col)*NTOK + n];
            } else {
                va = g_rel[(size_t)(h*64 + col - 64)*NTOK + n];
                vb = g_qkv[((size_t)b*768 + h*64 + col - 64)*NTOK + n];
            }
        }
        ta[ty + r*8][tx] = va;
        tb[ty + r*8][tx] = vb;
    }
    __syncthreads();
    #pragma unroll
    for (int r = 0; r < 4; r++) {
        int n = n0 + ty + r*8;
        size_t base = ((size_t)z*NPAD + n)*KSTACK;
        int col = c0 + tx;
        float va = ta[tx][ty + r*8];
        float vb = tb[tx][ty + r*8];
        __nv_bfloat16 ha = __float2bfloat16(va);
        __nv_bfloat16 la = __float2bfloat16(va - __bfloat162float(ha));
        __nv_bfloat16 hb = __float2bfloat16(vb);
        __nv_bfloat16 lb = __float2bfloat16(vb - __bfloat162float(hb));
        g_xa[base + col]       = ha;
        g_xa[base + 128 + col] = la;
        g_xa[base + 256 + col] = ha;
        g_yb[base + col]       = hb;
        g_yb[base + 128 + col] = hb;
        g_yb[base + 256 + col] = lb;
    }
}

// ---------------- V split ----------------
__global__ void vsplit() {
    __shared__ float t[32][33];
    const int m0 = blockIdx.x * 32, c0 = blockIdx.y * 32, z = blockIdx.z;
    const int b = z >> 2, h = z & 3;
    const int tx = threadIdx.x, ty = threadIdx.y;   // 32 x 8
    #pragma unroll
    for (int r = 0; r < 4; r++) {
        int c = c0 + ty + r*8;
        int m = m0 + tx;
        t[ty + r*8][tx] = (m < NTOK) ? g_qkv[((size_t)b*768 + 512 + h*64 + c)*NTOK + m] : 0.f;
    }
    __syncthreads();
    #pragma unroll
    for (int r = 0; r < 4; r++) {
        int m = m0 + ty + r*8;
        float v = t[tx][ty + r*8];
        __nv_bfloat16 hi = __float2bfloat16(v);
        __nv_bfloat16 lo = __float2bfloat16(v - __bfloat162float(hi));
        size_t idx = ((size_t)z*NPAD + m)*DHEAD + c0 + tx;
        g_vhi[idx] = hi;
        g_vlo[idx] = lo;
    }
}

// ---------------- HMMA S-tile kernel (128x128 tile, 64x32 warp tile, B x4) + row-max atomics ----------------
__global__ __launch_bounds__(256) void tn_s_mma() {
    __shared__ __nv_bfloat16 As[2][128*24];
    __shared__ __nv_bfloat16 Bs[2][128*24];
    const int tid = threadIdx.x;
    const int warp = tid >> 5, lane = tid & 31;
    const int wm = warp >> 2, wn = warp & 3;   // n rows wm*64, m cols wn*32
    const int z = blockIdx.z;
    const int n0 = blockIdx.y * 128, m0 = blockIdx.x * 128;

    const __nv_bfloat16* xa = g_xa + ((size_t)z*NPAD + n0)*KSTACK;
    const __nv_bfloat16* yb = g_yb + ((size_t)z*NPAD + m0)*KSTACK;

    const int lrow  = tid >> 1;
    const int lhalf = (tid & 1) * 8;

    const uint32_t sa_base = smem_u32(As);
    const uint32_t sb_base = smem_u32(Bs);

    float acc[4][4][4] = {};

    uint4 pa = *(const uint4*)(xa + (size_t)lrow*KSTACK + lhalf);
    uint4 pb = *(const uint4*)(yb + (size_t)lrow*KSTACK + lhalf);

    #pragma unroll 1
    for (int s = 0; s < 24; s++) {
        const int buf = s & 1;
        *(uint4*)&As[buf][lrow*24 + lhalf] = pa;
        *(uint4*)&Bs[buf][lrow*24 + lhalf] = pb;
        __syncthreads();

        if (s + 1 < 24) {
            const int k0 = (s + 1) * 16;
            pa = *(const uint4*)(xa + (size_t)lrow*KSTACK + k0 + lhalf);
            pb = *(const uint4*)(yb + (size_t)lrow*KSTACK + k0 + lhalf);
        }

        uint32_t afr[4][4];
        #pragma unroll
        for (int i = 0; i < 4; i++) {
            const int row = wm*64 + i*16 + (lane & 15);
            const uint32_t addr = sa_base + (uint32_t)(buf*128*24 + row*24 + (lane >> 4)*8) * 2;
            asm volatile("ldmatrix.sync.aligned.m8n8.x4.shared.b16 {%0,%1,%2,%3}, [%4];"
                : "=r"(afr[i][0]), "=r"(afr[i][1]), "=r"(afr[i][2]), "=r"(afr[i][3]) : "r"(addr));
        }
        uint32_t bfr[2][4];
        #pragma unroll
        for (int jp = 0; jp < 2; jp++) {
            const int row = wn*32 + jp*16 + (lane & 15);
            const uint32_t addr = sb_base + (uint32_t)(buf*128*24 + row*24 + (lane >> 4)*8) * 2;
            asm volatile("ldmatrix.sync.aligned.m8n8.x4.shared.b16 {%0,%1,%2,%3}, [%4];"
                : "=r"(bfr[jp][0]), "=r"(bfr[jp][1]), "=r"(bfr[jp][2]), "=r"(bfr[jp][3]) : "r"(addr));
        }
        #pragma unroll
        for (int i = 0; i < 4; i++)
            #pragma unroll
            for (int jp = 0; jp < 2; jp++) {
                asm volatile(
                    "mma.sync.aligned.m16n8k16.row.col.f32.bf16.bf16.f32 "
                    "{%0,%1,%2,%3}, {%4,%5,%6,%7}, {%8,%9}, {%0,%1,%2,%3};"
                    : "+f"(acc[i][2*jp][0]), "+f"(acc[i][2*jp][1]), "+f"(acc[i][2*jp][2]), "+f"(acc[i][2*jp][3])
                    : "r"(afr[i][0]), "r"(afr[i][1]), "r"(afr[i][2]), "r"(afr[i][3]),
                      "r"(bfr[jp][0]), "r"(bfr[jp][2]));
                asm volatile(
                    "mma.sync.aligned.m16n8k16.row.col.f32.bf16.bf16.f32 "
                    "{%0,%1,%2,%3}, {%4,%5,%6,%7}, {%8,%9}, {%0,%1,%2,%3};"
                    : "+f"(acc[i][2*jp+1][0]), "+f"(acc[i][2*jp+1][1]), "+f"(acc[i][2*jp+1][2]), "+f"(acc[i][2*jp+1][3])
                    : "r"(afr[i][0]), "r"(afr[i][1]), "r"(afr[i][2]), "r"(afr[i][3]),
                      "r"(bfr[jp][1]), "r"(bfr[jp][3]));
            }
    }

    float* C = g_S + (size_t)z*NTOK*NTOK;
    const int gr = lane >> 2, gc = (lane & 3) * 2;
    #pragma unroll
    for (int i = 0; i < 4; i++) {
        const int r0 = n0 + wm*64 + i*16 + gr;
        const int r1 = r0 + 8;
        float mr0 = -1e30f, mr1 = -1e30f;
        #pragma unroll
        for (int j = 0; j < 4; j++) {
            const int col = m0 + wn*32 + j*8 + gc;
            if (col < NTOK) {
                mr0 = fmaxf(mr0, acc[i][j][0]);
                mr1 = fmaxf(mr1, acc[i][j][2]);
                if (r0 < NTOK) *(float2*)&C[(size_t)r0*NTOK + col] = make_float2(acc[i][j][0], acc[i][j][1]);
                if (r1 < NTOK) *(float2*)&C[(size_t)r1*NTOK + col] = make_float2(acc[i][j][2], acc[i][j][3]);
            }
            if (col + 1 < NTOK) {
                mr0 = fmaxf(mr0, acc[i][j][1]);
                mr1 = fmaxf(mr1, acc[i][j][3]);
            }
        }
        mr0 = fmaxf(mr0, __shfl_xor_sync(0xffffffffu, mr0, 1));
        mr0 = fmaxf(mr0, __shfl_xor_sync(0xffffffffu, mr0, 2));
        mr1 = fmaxf(mr1, __shfl_xor_sync(0xffffffffu, mr1, 1));
        mr1 = fmaxf(mr1, __shfl_xor_sync(0xffffffffu, mr1, 2));
        if ((lane & 3) == 0) {
            if (r0 < NTOK) atomicMaxF(&g_rmax[z*NPAD + r0], mr0);
            if (r1 < NTOK) atomicMaxF(&g_rmax[z*NPAD + r1], mr1);
        }
    }
}

// ---------------- HMMA AV kernel: inline exp + inline row-sum, divide at end ----------------
__global__ __launch_bounds__(256) void av_mma() {
    extern __shared__ __nv_bfloat16 dsm[];
    __nv_bfloat16* Ahi = dsm;
    __nv_bfloat16* Alo = Ahi + 128*72;
    __nv_bfloat16* Bhi = Alo + 128*72;
    __nv_bfloat16* Blo = Bhi + 64*72;
    __shared__ float Ls[128][2];

    const int tid = threadIdx.x;
    const int warp = tid >> 5, lane = tid & 31;
    const int wn = warp >> 1, wd = warp & 1;
    const int z = blockIdx.y, b = z >> 2, h = z & 3;
    const int n0 = blockIdx.x * 128;

    const int lr = tid >> 1;
    const int lch = (tid & 1) * 32;
    const int n_ld = n0 + lr;
    const bool rowok = n_ld < NTOK;
    const float mx = rowok ? g_rmax[z*NPAD + n_ld] : 0.f;
    const float* Srow = g_S + (size_t)z*NTOK*NTOK + (size_t)n_ld*NTOK;

    const uint32_t sa_hi = smem_u32(Ahi);
    const uint32_t sa_lo = smem_u32(Alo);
    const uint32_t sb_hi = smem_u32(Bhi);
    const uint32_t sb_lo = smem_u32(Blo);

    float acc[2][4][4] = {};
    float lsum = 0.f;

    for (int ch = 0; ch < 43; ch++) {
        const int mc = ch * 64;
        __syncthreads();

        #pragma unroll
        for (int i = 0; i < 8; i++) {
            const int m = mc + lch + i*4;
            float4 pv = make_float4(0.f,0.f,0.f,0.f);
            if (rowok && m < NTOK) {
                float4 s = *(const float4*)(Srow + m);
                pv.x = exp2f((s.x - mx) * LOG2E);
                pv.y = exp2f((s.y - mx) * LOG2E);
                pv.z = exp2f((s.z - mx) * LOG2E);
                pv.w = exp2f((s.w - mx) * LOG2E);
                lsum += pv.x + pv.y + pv.z + pv.w;
            }
            __nv_bfloat162 h01 = __floats2bfloat162_rn(pv.x, pv.y);
            __nv_bfloat162 h23 = __floats2bfloat162_rn(pv.z, pv.w);
            __nv_bfloat162 l01 = __floats2bfloat162_rn(pv.x - __bfloat162float(__low2bfloat16(h01)),
                                                       pv.y - __bfloat162float(__high2bfloat16(h01)));
            __nv_bfloat162 l23 = __floats2bfloat162_rn(pv.z - __bfloat162float(__low2bfloat16(h23)),
                                                       pv.w - __bfloat162float(__high2bfloat16(h23)));
            const int o = lr*72 + lch + i*4;
            *(__nv_bfloat162*)(Ahi + o)     = h01;
            *(__nv_bfloat162*)(Ahi + o + 2) = h23;
            *(__nv_bfloat162*)(Alo + o)     = l01;
            *(__nv_bfloat162*)(Alo + o + 2) = l23;
        }
        #pragma unroll
        for (int i = 0; i < 2; i++) {
            const int idx = tid + 256*i;
            const int row = idx >> 3, seg = (idx & 7) * 8;
            const size_t gsrc = ((size_t)z*NPAD + mc + row)*DHEAD + seg;
            *(uint4*)(Bhi + row*72 + seg) = *(const uint4*)(g_vhi + gsrc);
            *(uint4*)(Blo + row*72 + seg) = *(const uint4*)(g_vlo + gsrc);
        }
        __syncthreads();

        #pragma unroll
        for (int step = 0; step < 4; step++) {
            const int k0 = step * 16;
            uint32_t ah[2][4], al[2][4];
            #pragma unroll
            for (int i = 0; i < 2; i++) {
                const uint32_t off = (uint32_t)((wn*32 + i*16 + (lane & 15))*72 + k0 + ((lane >> 4) << 3)) * 2;
                asm volatile("ldmatrix.sync.aligned.m8n8.x4.shared.b16 {%0,%1,%2,%3}, [%4];"
                    : "=r"(ah[i][0]), "=r"(ah[i][1]), "=r"(ah[i][2]), "=r"(ah[i][3]) : "r"(sa_hi + off));
                asm volatile("ldmatrix.sync.aligned.m8n8.x4.shared.b16 {%0,%1,%2,%3}, [%4];"
                    : "=r"(al[i][0]), "=r"(al[i][1]), "=r"(al[i][2]), "=r"(al[i][3]) : "r"(sa_lo + off));
            }
            uint32_t bh[2][4], bl[2][4];
            #pragma unroll
            for (int jj = 0; jj < 2; jj++) {
                const int d0 = wd*32 + jj*16;
                const uint32_t off = (uint32_t)((k0 + (lane & 7) + ((lane >> 3) & 1)*8)*72 + d0 + ((lane >> 4) << 3)) * 2;
                asm volatile("ldmatrix.sync.aligned.m8n8.x4.trans.shared.b16 {%0,%1,%2,%3}, [%4];"
                    : "=r"(bh[jj][0]), "=r"(bh[jj][1]), "=r"(bh[jj][2]), "=r"(bh[jj][3]) : "r"(sb_hi + off));
                asm volatile("ldmatrix.sync.aligned.m8n8.x4.trans.shared.b16 {%0,%1,%2,%3}, [%4];"
                    : "=r"(bl[jj][0]), "=r"(bl[jj][1]), "=r"(bl[jj][2]), "=r"(bl[jj][3]) : "r"(sb_lo + off));
            }
            #define AV_MMA(ac, af, b0, b1) \
                asm volatile("mma.sync.aligned.m16n8k16.row.col.f32.bf16.bf16.f32 " \
                    "{%0,%1,%2,%3}, {%4,%5,%6,%7}, {%8,%9}, {%0,%1,%2,%3};" \
                    : "+f"((ac)[0]), "+f"((ac)[1]), "+f"((ac)[2]), "+f"((ac)[3]) \
                    : "r"((af)[0]), "r"((af)[1]), "r"((af)[2]), "r"((af)[3]), "r"(b0), "r"(b1))
            #pragma unroll
            for (int i = 0; i < 2; i++)
                #pragma unroll
                for (int jj = 0; jj < 2; jj++) {
                    AV_MMA(acc[i][jj*2+0], ah[i], bh[jj][0], bh[jj][1]);
                    AV_MMA(acc[i][jj*2+1], ah[i], bh[jj][2], bh[jj][3]);
                    AV_MMA(acc[i][jj*2+0], al[i], bh[jj][0], bh[jj][1]);
                    AV_MMA(acc[i][jj*2+1], al[i], bh[jj][2], bh[jj][3]);
                    AV_MMA(acc[i][jj*2+0], ah[i], bl[jj][0], bl[jj][1]);
                    AV_MMA(acc[i][jj*2+1], ah[i], bl[jj][2], bl[jj][3]);
                }
            #undef AV_MMA
        }
    }

    Ls[lr][tid & 1] = lsum;
    __syncthreads();

    const int baseCh = b*CMID + h*DHEAD;
    const int gr = lane >> 2, gc = (lane & 3) * 2;
    #pragma unroll
    for (int i = 0; i < 2; i++) {
        const int lr0 = wn*32 + i*16 + gr;
        const int lr1 = lr0 + 8;
        const int r0 = n0 + lr0;
        const int r1 = n0 + lr1;
        const float inv0 = 1.f / (Ls[lr0][0] + Ls[lr0][1]);
        const float inv1 = 1.f / (Ls[lr1][0] + Ls[lr1][1]);
        #pragma unroll
        for (int j = 0; j < 4; j++) {
            const int d = wd*32 + j*8 + gc;
            float* c0p = g_ao + (size_t)(baseCh + d)*NTOK;
            float* c1p = g_ao + (size_t)(baseCh + d + 1)*NTOK;
            if (r0 < NTOK) { c0p[r0] = acc[i][j][0]*inv0; c1p[r0] = acc[i][j][1]*inv0; }
            if (r1 < NTOK) { c0p[r1] = acc[i][j][2]*inv1; c1p[r1] = acc[i][j][3]*inv1; }
        }
    }
}

// ---------------- BatchNorm ----------------
__global__ __launch_bounds__(256) void bn_stats(const float* __restrict__ x, int C,
                                                float* __restrict__ mean, float* __restrict__ istd) {
    const int c = blockIdx.x;
    const int tid = threadIdx.x;
    const int lane = tid & 31, wid = tid >> 5;
    float s = 0.f, sq = 0.f;
    for (int i = tid; i < BATCH*NTOK; i += 256) {
        int b = i / NTOK, n = i - b*NTOK;
        float v = x[((long)b*C + c)*NTOK + n];
        s += v; sq += v*v;
    }
    #pragma unroll
    for (int d = 16; d > 0; d >>= 1) {
        s  += __shfl_xor_sync(0xffffffffu, s, d);
        sq += __shfl_xor_sync(0xffffffffu, sq, d);
    }
    __shared__ float r1[8], r2[8];
    if (lane == 0) { r1[wid] = s; r2[wid] = sq; }
    __syncthreads();
    if (tid == 0) {
        float S1 = 0.f, S2 = 0.f;
        #pragma unroll
        for (int w = 0; w < 8; w++) { S1 += r1[w]; S2 += r2[w]; }
        const float inv_cnt = 1.f / (BATCH*NTOK);
        float m = S1 * inv_cnt;
        float var = S2 * inv_cnt - m*m;
        mean[c] = m;
        istd[c] = rsqrtf(var + 1e-5f);
    }
}

__global__ void bn_res_relu(const float* __restrict__ y, const float* __restrict__ xres,
                            float* __restrict__ out,
                            const float* __restrict__ mean, const float* __restrict__ istd,
                            const float* __restrict__ g, const float* __restrict__ bp) {
    long idx = (long)blockIdx.x * 256 + threadIdx.x;
    if (idx >= (long)BATCH*COUT*NTOK) return;
    int c = (int)((idx / NTOK) % COUT);
    float v = (y[idx] - mean[c]) * istd[c] * g[c] + bp[c] + xres[idx];
    out[idx] = fmaxf(v, 0.f);
}

// ---------------- launch ----------------
extern "C" void kernel_launch(void* const* d_in, const int* in_sizes, int n_in,
                              void* d_out, int out_size) {
    const float* x    = (const float*)d_in[0];
    const float* W1   = (const float*)d_in[1];
    const float* g1   = (const float*)d_in[2];
    const float* b1   = (const float*)d_in[3];
    const float* Wq   = (const float*)d_in[4];
    const float* bq   = (const float*)d_in[5];
    const float* Wk   = (const float*)d_in[6];
    const float* bk   = (const float*)d_in[7];
    const float* Wv   = (const float*)d_in[8];
    const float* bv   = (const float*)d_in[9];
    const float* relh = (const float*)d_in[10];
    const float* relw = (const float*)d_in[11];
    const float* reld = (const float*)d_in[12];
    const float* g2   = (const float*)d_in[13];
    const float* b2   = (const float*)d_in[14];
    const float* W3   = (const float*)d_in[15];
    const float* g3   = (const float*)d_in[16];
    const float* b3   = (const float*)d_in[17];
    float* out = (float*)d_out;

    float *y1, *ao, *y3, *mean, *istd, *qkv;
    __nv_bfloat16 *w1st, *wqkvst, *w3st, *xst, *y1st, *aost;
    cudaGetSymbolAddress((void**)&y1,  g_y1);
    cudaGetSymbolAddress((void**)&ao,  g_ao);
    cudaGetSymbolAddress((void**)&y3,  g_y3);
    cudaGetSymbolAddress((void**)&mean,g_mean);
    cudaGetSymbolAddress((void**)&istd,g_istd);
    cudaGetSymbolAddress((void**)&qkv, g_qkv);
    cudaGetSymbolAddress((void**)&w1st,  g_w1st);
    cudaGetSymbolAddress((void**)&wqkvst,g_wqkvst);
    cudaGetSymbolAddress((void**)&w3st,  g_w3st);
    cudaGetSymbolAddress((void**)&xst,   g_xst);
    cudaGetSymbolAddress((void**)&y1st,  g_y1st);
    cudaGetSymbolAddress((void**)&aost,  g_aost);

    const dim3 blk(256);
    const int NT = (NTOK + 127) / 128;        // 22
    const int NT32 = NPAD / 32;               // 88
    const int AV_SMEM = (2*128*72 + 2*64*72) * 2;
    cudaFuncSetAttribute(av_mma, cudaFuncAttributeMaxDynamicSharedMemorySize, AV_SMEM);

    // weight splits
    wsplit<<<(CMID*CIN + 255)/256, blk>>>(W1, w1st, CMID*CIN, CIN);
    wsplit<<<(CMID*CMID + 255)/256, blk>>>(Wq, wqkvst,                    CMID*CMID, CMID);
    wsplit<<<(CMID*CMID + 255)/256, blk>>>(Wk, wqkvst + (size_t)256*768,  CMID*CMID, CMID);
    wsplit<<<(CMID*CMID + 255)/256, blk>>>(Wv, wqkvst + (size_t)512*768,  CMID*CMID, CMID);
    wsplit<<<(COUT*CMID + 255)/256, blk>>>(W3, w3st, COUT*CMID, CMID);

    // x split -> conv1 (HMMA)
    xsplit<<<dim3(NT32, CIN/32, BATCH), dim3(32,8)>>>(x, xst, CIN,
        (long)CIN*NTOK, (long)NPAD*3*CIN, nullptr, nullptr, nullptr, nullptr);
    gemm_hmma<<<dim3(NT, 2, BATCH), blk>>>(w1st, xst, y1, 3*CIN,
        (long)NPAD*3*CIN, (long)CMID*NTOK, nullptr, nullptr, nullptr);
    bn_stats<<<CMID, 256>>>(y1, CMID, mean, istd);

    // BN1+ReLU fused into split -> qkv (HMMA, stacked M=768)
    xsplit<<<dim3(NT32, CMID/32, BATCH), dim3(32,8)>>>(y1, y1st, CMID,
        (long)CMID*NTOK, (long)NPAD*3*CMID, mean, istd, g1, b1);
    gemm_hmma<<<dim3(NT, 6, BATCH), blk>>>(wqkvst, y1st, qkv, 3*CMID,
        (long)NPAD*3*CMID, (long)768*NTOK, bq, bk, bv);

    // rel tensor + attention operand prep (build_xy also inits g_rmax)
    build_rel_kernel<<<(NHEADS*DHEAD*NTOK)/256, 256>>>(relh, relw, reld);
    build_xy<<<dim3(NT32, 4, BATCH*NHEADS), dim3(32,8)>>>();
    vsplit<<<dim3(NT32, 2, BATCH*NHEADS), dim3(32,8)>>>();

    // attention: logits+rowmax (HMMA) -> AV (HMMA, softmax+rowsum inline)
    tn_s_mma<<<dim3(NT, NT, BATCH*NHEADS), blk>>>();
    av_mma<<<dim3(NT, BATCH*NHEADS), blk, AV_SMEM>>>();

    // BN2+ReLU fused into split -> conv3 (HMMA)
    bn_stats<<<CMID, 256>>>(ao, CMID, mean, istd);
    xsplit<<<dim3(NT32, CMID/32, BATCH), dim3(32,8)>>>(ao, aost, CMID,
        (long)CMID*NTOK, (long)NPAD*3*CMID, mean, istd, g2, b2);
    gemm_hmma<<<dim3(NT, 8, BATCH), blk>>>(w3st, aost, y3, 3*CMID,
        (long)NPAD*3*CMID, (long)COUT*NTOK, nullptr, nullptr, nullptr);

    // BN3 + residual + ReLU
    bn_stats<<<COUT, 256>>>(y3, COUT, mean, istd);
    bn_res_relu<<<(BATCH*COUT*NTOK)/256, 256>>>(y3, x, out, mean, istd, g3, b3);
}

// round 15
// speedup vs baseline: 1.0767x; 1.0297x over previous
#include <cuda_runtime.h>
#include <cuda_bf16.h>
#include <cstdint>

#define NTOK   2744
#define NPAD   2816           // 22 * 128
#define KSTACK 384
#define BATCH  4
#define CMID   256
#define CIN    1024
#define COUT   1024
#define NHEADS 4
#define DHEAD  64
#define WDIM   14
#define LOG2E  1.44269504f

// ---------------- scratch (static device memory; no allocations) ----------------
__device__ float g_y1 [BATCH*CMID*NTOK];
__device__ float g_qkv[BATCH*3*CMID*NTOK];                 // [b][768][NTOK] (q|k|v)
__device__ float g_S  [(size_t)BATCH*NHEADS*NTOK*NTOK];    // ~482 MB
__device__ float g_ao [BATCH*CMID*NTOK];
__device__ float g_y3 [BATCH*COUT*NTOK];
__device__ float g_mean[1024];
__device__ float g_istd[1024];
__device__ __nv_bfloat16 g_xa[(size_t)BATCH*NHEADS*NPAD*KSTACK];   // [z][n][384]
__device__ __nv_bfloat16 g_yb[(size_t)BATCH*NHEADS*NPAD*KSTACK];   // [z][m][384]
__device__ __nv_bfloat16 g_vhi[(size_t)BATCH*NHEADS*NPAD*DHEAD];
__device__ __nv_bfloat16 g_vlo[(size_t)BATCH*NHEADS*NPAD*DHEAD];
__device__ float g_rmax [BATCH*NHEADS*NPAD];
// bf16-split GEMM operands
__device__ __nv_bfloat16 g_w1st  [(size_t)CMID*3*CIN];
__device__ __nv_bfloat16 g_wqkvst[(size_t)3*CMID*3*CMID];
__device__ __nv_bfloat16 g_w3st  [(size_t)COUT*3*CMID];
__device__ __nv_bfloat16 g_xst   [(size_t)BATCH*NPAD*3*CIN];
__device__ __nv_bfloat16 g_y1st  [(size_t)BATCH*NPAD*3*CMID];
__device__ __nv_bfloat16 g_aost  [(size_t)BATCH*NPAD*3*CMID];

__device__ __forceinline__ uint32_t smem_u32(const void* p) {
    uint32_t a;
    asm("{ .reg .u64 t; cvta.to.shared.u64 t, %1; cvt.u32.u64 %0, t; }" : "=r"(a) : "l"(p));
    return a;
}
__device__ __forceinline__ void atomicMaxF(float* addr, float val) {
    if (val >= 0.f) atomicMax((int*)addr, __float_as_int(val));
    else            atomicMin((unsigned int*)addr, __float_as_uint(val));
}

// ---------------- merged weight split: all 5 weight matrices -> [hi|lo|hi] stacks ----------------
// layout of work: idx in [0, 720896): conv1 [0, 262144), qkv [262144, 458752), conv3 [458752, 720896)
__global__ void wsplit_all(const float* __restrict__ W1,
                           const float* __restrict__ Wq, const float* __restrict__ Wk,
                           const float* __restrict__ Wv, const float* __restrict__ W3) {
    int idx = blockIdx.x * 256 + threadIdx.x;
    const float* W; __nv_bfloat16* Wst; int K, rel;
    if (idx < 262144)       { W = W1; Wst = g_w1st; K = CIN; rel = idx; }
    else if (idx < 458752)  {
        int r = idx - 262144;          // 3 * 65536
        int mat = r >> 16; rel = r & 65535;
        W = (mat == 0) ? Wq : (mat == 1) ? Wk : Wv;
        Wst = g_wqkvst + (size_t)mat * 256 * 768;
        K = CMID;
    }
    else if (idx < 720896)  { W = W3; Wst = g_w3st; K = CMID; rel = idx - 458752; }
    else return;
    int m = rel / K, k = rel - m*K;
    float v = W[rel];
    __nv_bfloat16 hi = __float2bfloat16(v);
    __nv_bfloat16 lo = __float2bfloat16(v - __bfloat162float(hi));
    size_t base = (size_t)m * 3 * K;
    Wst[base + k]       = hi;
    Wst[base + K + k]   = lo;
    Wst[base + 2*K + k] = hi;
}

// ---------------- activation split+transpose (+optional BN-ReLU) ----------------
__global__ void xsplit(const float* __restrict__ X, __nv_bfloat16* __restrict__ Xst,
                       int C, long strideX, long strideXst,
                       const float* __restrict__ mean, const float* __restrict__ istd,
                       const float* __restrict__ gam, const float* __restrict__ bet) {
    __shared__ float t[32][33];
    const int n0 = blockIdx.x * 32, c0 = blockIdx.y * 32, z = blockIdx.z;
    const int tx = threadIdx.x, ty = threadIdx.y;   // 32 x 8
    #pragma unroll
    for (int r = 0; r < 4; r++) {
        int c = c0 + ty + r*8;
        int n = n0 + tx;
        float v = 0.f;
        if (n < NTOK) {
            v = X[z*strideX + (size_t)c*NTOK + n];
            if (mean) v = fmaxf((v - mean[c]) * istd[c] * gam[c] + bet[c], 0.f);
        }
        t[ty + r*8][tx] = v;
    }
    __syncthreads();
    #pragma unroll
    for (int r = 0; r < 4; r++) {
        int n = n0 + ty + r*8;
        int c = c0 + tx;
        float v = t[tx][ty + r*8];
        __nv_bfloat16 hi = __float2bfloat16(v);
        __nv_bfloat16 lo = __float2bfloat16(v - __bfloat162float(hi));
        size_t base = z*strideXst + (size_t)n * (3*C);
        Xst[base + c]       = hi;
        Xst[base + C + c]   = hi;
        Xst[base + 2*C + c] = lo;
    }
}

// ---------------- generic HMMA GEMM (convs/qkv), 32-k chunks, B via x4 ----------------
__global__ __launch_bounds__(256) void gemm_hmma(
    const __nv_bfloat16* __restrict__ A, const __nv_bfloat16* __restrict__ B,
    float* __restrict__ C, int Ks, long strideB, long strideC,
    const float* __restrict__ bias0, const float* __restrict__ bias1,
    const float* __restrict__ bias2)
{
    __shared__ __nv_bfloat16 As[2][2][128*24];
    __shared__ __nv_bfloat16 Bs[2][2][128*24];
    const int tid = threadIdx.x;
    const int warp = tid >> 5, lane = tid & 31;
    const int wm = warp >> 2, wn = warp & 3;
    const int z = blockIdx.z;
    const int bm = blockIdx.y * 128, n0 = blockIdx.x * 128;

    const __nv_bfloat16* gA = A + (size_t)(bm + (tid >> 1))*Ks;
    const __nv_bfloat16* gB = B + z*strideB + (size_t)(n0 + (tid >> 1))*Ks;
    const int lrow  = tid >> 1;
    const int lhalf = (tid & 1) * 8;

    const uint32_t sa_base = smem_u32(As);
    const uint32_t sb_base = smem_u32(Bs);

    float acc[4][4][4] = {};
    const int chunks = Ks >> 5;

    uint4 pa0 = *(const uint4*)(gA + lhalf);
    uint4 pa1 = *(const uint4*)(gA + 16 + lhalf);
    uint4 pb0 = *(const uint4*)(gB + lhalf);
    uint4 pb1 = *(const uint4*)(gB + 16 + lhalf);

    #pragma unroll 1
    for (int s = 0; s < chunks; s++) {
        const int buf = s & 1;
        *(uint4*)&As[buf][0][lrow*24 + lhalf] = pa0;
        *(uint4*)&As[buf][1][lrow*24 + lhalf] = pa1;
        *(uint4*)&Bs[buf][0][lrow*24 + lhalf] = pb0;
        *(uint4*)&Bs[buf][1][lrow*24 + lhalf] = pb1;
        __syncthreads();

        if (s + 1 < chunks) {
            const int k0 = (s + 1) * 32;
            pa0 = *(const uint4*)(gA + k0 + lhalf);
            pa1 = *(const uint4*)(gA + k0 + 16 + lhalf);
            pb0 = *(const uint4*)(gB + k0 + lhalf);
            pb1 = *(const uint4*)(gB + k0 + 16 + lhalf);
        }

        #pragma unroll
        for (int ss = 0; ss < 2; ss++) {
            const uint32_t abase = sa_base + (uint32_t)(buf*2 + ss) * (128*24*2);
            const uint32_t bbase = sb_base + (uint32_t)(buf*2 + ss) * (128*24*2);
            uint32_t afr[4][4];
            #pragma unroll
            for (int i = 0; i < 4; i++) {
                const int row = wm*64 + i*16 + (lane & 15);
                const uint32_t addr = abase + (uint32_t)(row*24 + (lane >> 4)*8) * 2;
                asm volatile("ldmatrix.sync.aligned.m8n8.x4.shared.b16 {%0,%1,%2,%3}, [%4];"
                    : "=r"(afr[i][0]), "=r"(afr[i][1]), "=r"(afr[i][2]), "=r"(afr[i][3]) : "r"(addr));
            }
            uint32_t bfr[2][4];
            #pragma unroll
            for (int jp = 0; jp < 2; jp++) {
                const int row = wn*32 + jp*16 + (lane & 15);
                const uint32_t addr = bbase + (uint32_t)(row*24 + (lane >> 4)*8) * 2;
                asm volatile("ldmatrix.sync.aligned.m8n8.x4.shared.b16 {%0,%1,%2,%3}, [%4];"
                    : "=r"(bfr[jp][0]), "=r"(bfr[jp][1]), "=r"(bfr[jp][2]), "=r"(bfr[jp][3]) : "r"(addr));
            }
            #pragma unroll
            for (int i = 0; i < 4; i++)
                #pragma unroll
                for (int jp = 0; jp < 2; jp++) {
                    asm volatile(
                        "mma.sync.aligned.m16n8k16.row.col.f32.bf16.bf16.f32 "
                        "{%0,%1,%2,%3}, {%4,%5,%6,%7}, {%8,%9}, {%0,%1,%2,%3};"
                        : "+f"(acc[i][2*jp][0]), "+f"(acc[i][2*jp][1]), "+f"(acc[i][2*jp][2]), "+f"(acc[i][2*jp][3])
                        : "r"(afr[i][0]), "r"(afr[i][1]), "r"(afr[i][2]), "r"(afr[i][3]),
                          "r"(bfr[jp][0]), "r"(bfr[jp][2]));
                    asm volatile(
                        "mma.sync.aligned.m16n8k16.row.col.f32.bf16.bf16.f32 "
                        "{%0,%1,%2,%3}, {%4,%5,%6,%7}, {%8,%9}, {%0,%1,%2,%3};"
                        : "+f"(acc[i][2*jp+1][0]), "+f"(acc[i][2*jp+1][1]), "+f"(acc[i][2*jp+1][2]), "+f"(acc[i][2*jp+1][3])
                        : "r"(afr[i][0]), "r"(afr[i][1]), "r"(afr[i][2]), "r"(afr[i][3]),
                          "r"(bfr[jp][1]), "r"(bfr[jp][3]));
                }
        }
    }

    float* Cz = C + z*strideC;
    const int gr = lane >> 2, gc = (lane & 3) * 2;
    #pragma unroll
    for (int i = 0; i < 4; i++) {
        const int r0 = bm + wm*64 + i*16 + gr;
        const int r1 = r0 + 8;
        float bi0 = 0.f, bi1 = 0.f;
        if (bias0) {
            const float* bp0 = (r0 < 256) ? bias0 : (r0 < 512) ? bias1 : bias2;
            const float* bp1 = (r1 < 256) ? bias0 : (r1 < 512) ? bias1 : bias2;
            bi0 = bp0[r0 & 255];
            bi1 = bp1[r1 & 255];
        }
        #pragma unroll
        for (int j = 0; j < 4; j++) {
            const int col = n0 + wn*32 + j*8 + gc;
            if (col < NTOK) {
                *(float2*)&Cz[(size_t)r0*NTOK + col] = make_float2(acc[i][j][0] + bi0, acc[i][j][1] + bi0);
                *(float2*)&Cz[(size_t)r1*NTOK + col] = make_float2(acc[i][j][2] + bi1, acc[i][j][3] + bi1);
            }
        }
    }
}

// ---------------- build bf16-split stacked operands (rel computed inline) + init g_rmax ----------------
__global__ void build_xy(const float* __restrict__ rh,
                         const float* __restrict__ rw,
                         const float* __restrict__ rd) {
    __shared__ float ta[32][33], tb[32][33];
    const int n0 = blockIdx.x * 32, c0 = blockIdx.y * 32, z = blockIdx.z;
    const int b = z >> 2, h = z & 3;
    const int tx = threadIdx.x, ty = threadIdx.y;    // 32 x 8
    if (blockIdx.y == 0 && ty == 0) g_rmax[z*NPAD + n0 + tx] = -1e30f;
    #pragma unroll
    for (int r = 0; r < 4; r++) {
        int col = c0 + ty + r*8;
        int n = n0 + tx;
        float va = 0.f, vb = 0.f;
        if (n < NTOK) {
            if (col < 64) {
                va = g_qkv[((size_t)b*768 + h*64 + col)*NTOK + n];
                vb = g_qkv[((size_t)b*768 + 256 + h*64 + col)*NTOK + n];
            } else {
                const int hd = h*64 + col - 64;
                const int w  = n / (WDIM*WDIM);
                const int hh = (n / WDIM) % WDIM;
                const int dd = n % WDIM;
                va = rh[(hd*WDIM + hh)*WDIM + dd]
                   + rw[(hd*WDIM + w )*WDIM + dd]
                   + rd[(hd*WDIM + w )*WDIM + hh];
                vb = g_qkv[((size_t)b*768 + h*64 + col - 64)*NTOK + n];
            }
        }
        ta[ty + r*8][tx] = va;
        tb[ty + r*8][tx] = vb;
    }
    __syncthreads();
    #pragma unroll
    for (int r = 0; r < 4; r++) {
        int n = n0 + ty + r*8;
        size_t base = ((size_t)z*NPAD + n)*KSTACK;
        int col = c0 + tx;
        float va = ta[tx][ty + r*8];
        float vb = tb[tx][ty + r*8];
        __nv_bfloat16 ha = __float2bfloat16(va);
        __nv_bfloat16 la = __float2bfloat16(va - __bfloat162float(ha));
        __nv_bfloat16 hb = __float2bfloat16(vb);
        __nv_bfloat16 lb = __float2bfloat16(vb - __bfloat162float(hb));
        g_xa[base + col]       = ha;
        g_xa[base + 128 + col] = la;
        g_xa[base + 256 + col] = ha;
        g_yb[base + col]       = hb;
        g_yb[base + 128 + col] = hb;
        g_yb[base + 256 + col] = lb;
    }
}

// ---------------- V split ----------------
__global__ void vsplit() {
    __shared__ float t[32][33];
    const int m0 = blockIdx.x * 32, c0 = blockIdx.y * 32, z = blockIdx.z;
    const int b = z >> 2, h = z & 3;
    const int tx = threadIdx.x, ty = threadIdx.y;   // 32 x 8
    #pragma unroll
    for (int r = 0; r < 4; r++) {
        int c = c0 + ty + r*8;
        int m = m0 + tx;
        t[ty + r*8][tx] = (m < NTOK) ? g_qkv[((size_t)b*768 + 512 + h*64 + c)*NTOK + m] : 0.f;
    }
    __syncthreads();
    #pragma unroll
    for (int r = 0; r < 4; r++) {
        int m = m0 + ty + r*8;
        float v = t[tx][ty + r*8];
        __nv_bfloat16 hi = __float2bfloat16(v);
        __nv_bfloat16 lo = __float2bfloat16(v - __bfloat162float(hi));
        size_t idx = ((size_t)z*NPAD + m)*DHEAD + c0 + tx;
        g_vhi[idx] = hi;
        g_vlo[idx] = lo;
    }
}

// ---------------- HMMA S-tile kernel (128x128 tile, 32-k chunks, B x4) + row-max atomics ----------------
__global__ __launch_bounds__(256) void tn_s_mma() {
    __shared__ __nv_bfloat16 As[2][2][128*24];
    __shared__ __nv_bfloat16 Bs[2][2][128*24];
    const int tid = threadIdx.x;
    const int warp = tid >> 5, lane = tid & 31;
    const int wm = warp >> 2, wn = warp & 3;   // n rows wm*64, m cols wn*32
    const int z = blockIdx.z;
    const int n0 = blockIdx.y * 128, m0 = blockIdx.x * 128;

    const __nv_bfloat16* xa = g_xa + ((size_t)z*NPAD + n0)*KSTACK;
    const __nv_bfloat16* yb = g_yb + ((size_t)z*NPAD + m0)*KSTACK;

    const int lrow  = tid >> 1;
    const int lhalf = (tid & 1) * 8;
    const __nv_bfloat16* gA = xa + (size_t)lrow*KSTACK + lhalf;
    const __nv_bfloat16* gB = yb + (size_t)lrow*KSTACK + lhalf;

    const uint32_t sa_base = smem_u32(As);
    const uint32_t sb_base = smem_u32(Bs);

    float acc[4][4][4] = {};

    uint4 pa0 = *(const uint4*)(gA);
    uint4 pa1 = *(const uint4*)(gA + 16);
    uint4 pb0 = *(const uint4*)(gB);
    uint4 pb1 = *(const uint4*)(gB + 16);

    #pragma unroll 1
    for (int s = 0; s < 12; s++) {
        const int buf = s & 1;
        *(uint4*)&As[buf][0][lrow*24 + lhalf] = pa0;
        *(uint4*)&As[buf][1][lrow*24 + lhalf] = pa1;
        *(uint4*)&Bs[buf][0][lrow*24 + lhalf] = pb0;
        *(uint4*)&Bs[buf][1][lrow*24 + lhalf] = pb1;
        __syncthreads();

        if (s + 1 < 12) {
            const int k0 = (s + 1) * 32;
            pa0 = *(const uint4*)(gA + k0);
            pa1 = *(const uint4*)(gA + k0 + 16);
            pb0 = *(const uint4*)(gB + k0);
            pb1 = *(const uint4*)(gB + k0 + 16);
        }

        #pragma unroll
        for (int ss = 0; ss < 2; ss++) {
            const uint32_t abase = sa_base + (uint32_t)(buf*2 + ss) * (128*24*2);
            const uint32_t bbase = sb_base + (uint32_t)(buf*2 + ss) * (128*24*2);
            uint32_t afr[4][4];
            #pragma unroll
            for (int i = 0; i < 4; i++) {
                const int row = wm*64 + i*16 + (lane & 15);
                const uint32_t addr = abase + (uint32_t)(row*24 + (lane >> 4)*8) * 2;
                asm volatile("ldmatrix.sync.aligned.m8n8.x4.shared.b16 {%0,%1,%2,%3}, [%4];"
                    : "=r"(afr[i][0]), "=r"(afr[i][1]), "=r"(afr[i][2]), "=r"(afr[i][3]) : "r"(addr));
            }
            uint32_t bfr[2][4];
            #pragma unroll
            for (int jp = 0; jp < 2; jp++) {
                const int row = wn*32 + jp*16 + (lane & 15);
                const uint32_t addr = bbase + (uint32_t)(row*24 + (lane >> 4)*8) * 2;
                asm volatile("ldmatrix.sync.aligned.m8n8.x4.shared.b16 {%0,%1,%2,%3}, [%4];"
                    : "=r"(bfr[jp][0]), "=r"(bfr[jp][1]), "=r"(bfr[jp][2]), "=r"(bfr[jp][3]) : "r"(addr));
            }
            #pragma unroll
            for (int i = 0; i < 4; i++)
                #pragma unroll
                for (int jp = 0; jp < 2; jp++) {
                    asm volatile(
                        "mma.sync.aligned.m16n8k16.row.col.f32.bf16.bf16.f32 "
                        "{%0,%1,%2,%3}, {%4,%5,%6,%7}, {%8,%9}, {%0,%1,%2,%3};"
                        : "+f"(acc[i][2*jp][0]), "+f"(acc[i][2*jp][1]), "+f"(acc[i][2*jp][2]), "+f"(acc[i][2*jp][3])
                        : "r"(afr[i][0]), "r"(afr[i][1]), "r"(afr[i][2]), "r"(afr[i][3]),
                          "r"(bfr[jp][0]), "r"(bfr[jp][2]));
                    asm volatile(
                        "mma.sync.aligned.m16n8k16.row.col.f32.bf16.bf16.f32 "
                        "{%0,%1,%2,%3}, {%4,%5,%6,%7}, {%8,%9}, {%0,%1,%2,%3};"
                        : "+f"(acc[i][2*jp+1][0]), "+f"(acc[i][2*jp+1][1]), "+f"(acc[i][2*jp+1][2]), "+f"(acc[i][2*jp+1][3])
                        : "r"(afr[i][0]), "r"(afr[i][1]), "r"(afr[i][2]), "r"(afr[i][3]),
                          "r"(bfr[jp][1]), "r"(bfr[jp][3]));
                }
        }
    }

    float* C = g_S + (size_t)z*NTOK*NTOK;
    const int gr = lane >> 2, gc = (lane & 3) * 2;
    #pragma unroll
    for (int i = 0; i < 4; i++) {
        const int r0 = n0 + wm*64 + i*16 + gr;
        const int r1 = r0 + 8;
        float mr0 = -1e30f, mr1 = -1e30f;
        #pragma unroll
        for (int j = 0; j < 4; j++) {
            const int col = m0 + wn*32 + j*8 + gc;
            if (col < NTOK) {
                mr0 = fmaxf(mr0, acc[i][j][0]);
                mr1 = fmaxf(mr1, acc[i][j][2]);
                if (r0 < NTOK) *(float2*)&C[(size_t)r0*NTOK + col] = make_float2(acc[i][j][0], acc[i][j][1]);
                if (r1 < NTOK) *(float2*)&C[(size_t)r1*NTOK + col] = make_float2(acc[i][j][2], acc[i][j][3]);
            }
            if (col + 1 < NTOK) {
                mr0 = fmaxf(mr0, acc[i][j][1]);
                mr1 = fmaxf(mr1, acc[i][j][3]);
            }
        }
        mr0 = fmaxf(mr0, __shfl_xor_sync(0xffffffffu, mr0, 1));
        mr0 = fmaxf(mr0, __shfl_xor_sync(0xffffffffu, mr0, 2));
        mr1 = fmaxf(mr1, __shfl_xor_sync(0xffffffffu, mr1, 1));
        mr1 = fmaxf(mr1, __shfl_xor_sync(0xffffffffu, mr1, 2));
        if ((lane & 3) == 0) {
            if (r0 < NTOK) atomicMaxF(&g_rmax[z*NPAD + r0], mr0);
            if (r1 < NTOK) atomicMaxF(&g_rmax[z*NPAD + r1], mr1);
        }
    }
}

// ---------------- HMMA AV kernel: inline exp + inline row-sum, divide at end ----------------
__global__ __launch_bounds__(256) void av_mma() {
    extern __shared__ __nv_bfloat16 dsm[];
    __nv_bfloat16* Ahi = dsm;
    __nv_bfloat16* Alo = Ahi + 128*72;
    __nv_bfloat16* Bhi = Alo + 128*72;
    __nv_bfloat16* Blo = Bhi + 64*72;
    __shared__ float Ls[128][2];

    const int tid = threadIdx.x;
    const int warp = tid >> 5, lane = tid & 31;
    const int wn = warp >> 1, wd = warp & 1;
    const int z = blockIdx.y, b = z >> 2, h = z & 3;
    const int n0 = blockIdx.x * 128;

    const int lr = tid >> 1;
    const int lch = (tid & 1) * 32;
    const int n_ld = n0 + lr;
    const bool rowok = n_ld < NTOK;
    const float mx = rowok ? g_rmax[z*NPAD + n_ld] : 0.f;
    const float* Srow = g_S + (size_t)z*NTOK*NTOK + (size_t)n_ld*NTOK;

    const uint32_t sa_hi = smem_u32(Ahi);
    const uint32_t sa_lo = smem_u32(Alo);
    const uint32_t sb_hi = smem_u32(Bhi);
    const uint32_t sb_lo = smem_u32(Blo);

    float acc[2][4][4] = {};
    float lsum = 0.f;

    for (int ch = 0; ch < 43; ch++) {
        const int mc = ch * 64;
        __syncthreads();

        #pragma unroll
        for (int i = 0; i < 8; i++) {
            const int m = mc + lch + i*4;
            float4 pv = make_float4(0.f,0.f,0.f,0.f);
            if (rowok && m < NTOK) {
                float4 s = *(const float4*)(Srow + m);
                pv.x = exp2f((s.x - mx) * LOG2E);
                pv.y = exp2f((s.y - mx) * LOG2E);
                pv.z = exp2f((s.z - mx) * LOG2E);
                pv.w = exp2f((s.w - mx) * LOG2E);
                lsum += pv.x + pv.y + pv.z + pv.w;
            }
            __nv_bfloat162 h01 = __floats2bfloat162_rn(pv.x, pv.y);
            __nv_bfloat162 h23 = __floats2bfloat162_rn(pv.z, pv.w);
            __nv_bfloat162 l01 = __floats2bfloat162_rn(pv.x - __bfloat162float(__low2bfloat16(h01)),
                                                       pv.y - __bfloat162float(__high2bfloat16(h01)));
            __nv_bfloat162 l23 = __floats2bfloat162_rn(pv.z - __bfloat162float(__low2bfloat16(h23)),
                                                       pv.w - __bfloat162float(__high2bfloat16(h23)));
            const int o = lr*72 + lch + i*4;
            *(__nv_bfloat162*)(Ahi + o)     = h01;
            *(__nv_bfloat162*)(Ahi + o + 2) = h23;
            *(__nv_bfloat162*)(Alo + o)     = l01;
            *(__nv_bfloat162*)(Alo + o + 2) = l23;
        }
        #pragma unroll
        for (int i = 0; i < 2; i++) {
            const int idx = tid + 256*i;
            const int row = idx >> 3, seg = (idx & 7) * 8;
            const size_t gsrc = ((size_t)z*NPAD + mc + row)*DHEAD + seg;
            *(uint4*)(Bhi + row*72 + seg) = *(const uint4*)(g_vhi + gsrc);
            *(uint4*)(Blo + row*72 + seg) = *(const uint4*)(g_vlo + gsrc);
        }
        __syncthreads();

        #pragma unroll
        for (int step = 0; step < 4; step++) {
            const int k0 = step * 16;
            uint32_t ah[2][4], al[2][4];
            #pragma unroll
            for (int i = 0; i < 2; i++) {
                const uint32_t off = (uint32_t)((wn*32 + i*16 + (lane & 15))*72 + k0 + ((lane >> 4) << 3)) * 2;
                asm volatile("ldmatrix.sync.aligned.m8n8.x4.shared.b16 {%0,%1,%2,%3}, [%4];"
                    : "=r"(ah[i][0]), "=r"(ah[i][1]), "=r"(ah[i][2]), "=r"(ah[i][3]) : "r"(sa_hi + off));
                asm volatile("ldmatrix.sync.aligned.m8n8.x4.shared.b16 {%0,%1,%2,%3}, [%4];"
                    : "=r"(al[i][0]), "=r"(al[i][1]), "=r"(al[i][2]), "=r"(al[i][3]) : "r"(sa_lo + off));
            }
            uint32_t bh[2][4], bl[2][4];
            #pragma unroll
            for (int jj = 0; jj < 2; jj++) {
                const int d0 = wd*32 + jj*16;
                const uint32_t off = (uint32_t)((k0 + (lane & 7) + ((lane >> 3) & 1)*8)*72 + d0 + ((lane >> 4) << 3)) * 2;
                asm volatile("ldmatrix.sync.aligned.m8n8.x4.trans.shared.b16 {%0,%1,%2,%3}, [%4];"
                    : "=r"(bh[jj][0]), "=r"(bh[jj][1]), "=r"(bh[jj][2]), "=r"(bh[jj][3]) : "r"(sb_hi + off));
                asm volatile("ldmatrix.sync.aligned.m8n8.x4.trans.shared.b16 {%0,%1,%2,%3}, [%4];"
                    : "=r"(bl[jj][0]), "=r"(bl[jj][1]), "=r"(bl[jj][2]), "=r"(bl[jj][3]) : "r"(sb_lo + off));
            }
            #define AV_MMA(ac, af, b0, b1) \
                asm volatile("mma.sync.aligned.m16n8k16.row.col.f32.bf16.bf16.f32 " \
                    "{%0,%1,%2,%3}, {%4,%5,%6,%7}, {%8,%9}, {%0,%1,%2,%3};" \
                    : "+f"((ac)[0]), "+f"((ac)[1]), "+f"((ac)[2]), "+f"((ac)[3]) \
                    : "r"((af)[0]), "r"((af)[1]), "r"((af)[2]), "r"((af)[3]), "r"(b0), "r"(b1))
            #pragma unroll
            for (int i = 0; i < 2; i++)
                #pragma unroll
                for (int jj = 0; jj < 2; jj++) {
                    AV_MMA(acc[i][jj*2+0], ah[i], bh[jj][0], bh[jj][1]);
                    AV_MMA(acc[i][jj*2+1], ah[i], bh[jj][2], bh[jj][3]);
                    AV_MMA(acc[i][jj*2+0], al[i], bh[jj][0], bh[jj][1]);
                    AV_MMA(acc[i][jj*2+1], al[i], bh[jj][2], bh[jj][3]);
                    AV_MMA(acc[i][jj*2+0], ah[i], bl[jj][0], bl[jj][1]);
                    AV_MMA(acc[i][jj*2+1], ah[i], bl[jj][2], bl[jj][3]);
                }
            #undef AV_MMA
        }
    }

    Ls[lr][tid & 1] = lsum;
    __syncthreads();

    const int baseCh = b*CMID + h*DHEAD;
    const int gr = lane >> 2, gc = (lane & 3) * 2;
    #pragma unroll
    for (int i = 0; i < 2; i++) {
        const int lr0 = wn*32 + i*16 + gr;
        const int lr1 = lr0 + 8;
        const int r0 = n0 + lr0;
        const int r1 = n0 + lr1;
        const float inv0 = 1.f / (Ls[lr0][0] + Ls[lr0][1]);
        const float inv1 = 1.f / (Ls[lr1][0] + Ls[lr1][1]);
        #pragma unroll
        for (int j = 0; j < 4; j++) {
            const int d = wd*32 + j*8 + gc;
            float* c0p = g_ao + (size_t)(baseCh + d)*NTOK;
            float* c1p = g_ao + (size_t)(baseCh + d + 1)*NTOK;
            if (r0 < NTOK) { c0p[r0] = acc[i][j][0]*inv0; c1p[r0] = acc[i][j][1]*inv0; }
            if (r1 < NTOK) { c0p[r1] = acc[i][j][2]*inv1; c1p[r1] = acc[i][j][3]*inv1; }
        }
    }
}

// ---------------- BatchNorm ----------------
__global__ __launch_bounds__(256) void bn_stats(const float* __restrict__ x, int C,
                                                float* __restrict__ mean, float* __restrict__ istd) {
    const int c = blockIdx.x;
    const int tid = threadIdx.x;
    const int lane = tid & 31, wid = tid >> 5;
    float s = 0.f, sq = 0.f;
    for (int i = tid; i < BATCH*NTOK; i += 256) {
        int b = i / NTOK, n = i - b*NTOK;
        float v = x[((long)b*C + c)*NTOK + n];
        s += v; sq += v*v;
    }
    #pragma unroll
    for (int d = 16; d > 0; d >>= 1) {
        s  += __shfl_xor_sync(0xffffffffu, s, d);
        sq += __shfl_xor_sync(0xffffffffu, sq, d);
    }
    __shared__ float r1[8], r2[8];
    if (lane == 0) { r1[wid] = s; r2[wid] = sq; }
    __syncthreads();
    if (tid == 0) {
        float S1 = 0.f, S2 = 0.f;
        #pragma unroll
        for (int w = 0; w < 8; w++) { S1 += r1[w]; S2 += r2[w]; }
        const float inv_cnt = 1.f / (BATCH*NTOK);
        float m = S1 * inv_cnt;
        float var = S2 * inv_cnt - m*m;
        mean[c] = m;
        istd[c] = rsqrtf(var + 1e-5f);
    }
}

__global__ void bn_res_relu(const float* __restrict__ y, const float* __restrict__ xres,
                            float* __restrict__ out,
                            const float* __restrict__ mean, const float* __restrict__ istd,
                            const float* __restrict__ g, const float* __restrict__ bp) {
    long idx = (long)blockIdx.x * 256 + threadIdx.x;
    if (idx >= (long)BATCH*COUT*NTOK) return;
    int c = (int)((idx / NTOK) % COUT);
    float v = (y[idx] - mean[c]) * istd[c] * g[c] + bp[c] + xres[idx];
    out[idx] = fmaxf(v, 0.f);
}

// ---------------- launch ----------------
extern "C" void kernel_launch(void* const* d_in, const int* in_sizes, int n_in,
                              void* d_out, int out_size) {
    const float* x    = (const float*)d_in[0];
    const float* W1   = (const float*)d_in[1];
    const float* g1   = (const float*)d_in[2];
    const float* b1   = (const float*)d_in[3];
    const float* Wq   = (const float*)d_in[4];
    const float* bq   = (const float*)d_in[5];
    const float* Wk   = (const float*)d_in[6];
    const float* bk   = (const float*)d_in[7];
    const float* Wv   = (const float*)d_in[8];
    const float* bv   = (const float*)d_in[9];
    const float* relh = (const float*)d_in[10];
    const float* relw = (const float*)d_in[11];
    const float* reld = (const float*)d_in[12];
    const float* g2   = (const float*)d_in[13];
    const float* b2   = (const float*)d_in[14];
    const float* W3   = (const float*)d_in[15];
    const float* g3   = (const float*)d_in[16];
    const float* b3   = (const float*)d_in[17];
    float* out = (float*)d_out;

    float *y1, *ao, *y3, *mean, *istd, *qkv;
    __nv_bfloat16 *w1st, *wqkvst, *w3st, *xst, *y1st, *aost;
    cudaGetSymbolAddress((void**)&y1,  g_y1);
    cudaGetSymbolAddress((void**)&ao,  g_ao);
    cudaGetSymbolAddress((void**)&y3,  g_y3);
    cudaGetSymbolAddress((void**)&mean,g_mean);
    cudaGetSymbolAddress((void**)&istd,g_istd);
    cudaGetSymbolAddress((void**)&qkv, g_qkv);
    cudaGetSymbolAddress((void**)&w1st,  g_w1st);
    cudaGetSymbolAddress((void**)&wqkvst,g_wqkvst);
    cudaGetSymbolAddress((void**)&w3st,  g_w3st);
    cudaGetSymbolAddress((void**)&xst,   g_xst);
    cudaGetSymbolAddress((void**)&y1st,  g_y1st);
    cudaGetSymbolAddress((void**)&aost,  g_aost);

    const dim3 blk(256);
    const int NT = (NTOK + 127) / 128;        // 22
    const int NT32 = NPAD / 32;               // 88
    const int AV_SMEM = (2*128*72 + 2*64*72) * 2;
    cudaFuncSetAttribute(av_mma, cudaFuncAttributeMaxDynamicSharedMemorySize, AV_SMEM);

    // merged weight splits (1 launch)
    wsplit_all<<<(720896 + 255)/256, blk>>>(W1, Wq, Wk, Wv, W3);

    // x split -> conv1 (HMMA)
    xsplit<<<dim3(NT32, CIN/32, BATCH), dim3(32,8)>>>(x, xst, CIN,
        (long)CIN*NTOK, (long)NPAD*3*CIN, nullptr, nullptr, nullptr, nullptr);
    gemm_hmma<<<dim3(NT, 2, BATCH), blk>>>(w1st, xst, y1, 3*CIN,
        (long)NPAD*3*CIN, (long)CMID*NTOK, nullptr, nullptr, nullptr);
    bn_stats<<<CMID, 256>>>(y1, CMID, mean, istd);

    // BN1+ReLU fused into split -> qkv (HMMA, stacked M=768)
    xsplit<<<dim3(NT32, CMID/32, BATCH), dim3(32,8)>>>(y1, y1st, CMID,
        (long)CMID*NTOK, (long)NPAD*3*CMID, mean, istd, g1, b1);
    gemm_hmma<<<dim3(NT, 6, BATCH), blk>>>(wqkvst, y1st, qkv, 3*CMID,
        (long)NPAD*3*CMID, (long)768*NTOK, bq, bk, bv);

    // attention operand prep (build_xy computes rel inline + inits g_rmax)
    build_xy<<<dim3(NT32, 4, BATCH*NHEADS), dim3(32,8)>>>(relh, relw, reld);
    vsplit<<<dim3(NT32, 2, BATCH*NHEADS), dim3(32,8)>>>();

    // attention: logits+rowmax (HMMA) -> AV (HMMA, softmax+rowsum inline)
    tn_s_mma<<<dim3(NT, NT, BATCH*NHEADS), blk>>>();
    av_mma<<<dim3(NT, BATCH*NHEADS), blk, AV_SMEM>>>();

    // BN2+ReLU fused into split -> conv3 (HMMA)
    bn_stats<<<CMID, 256>>>(ao, CMID, mean, istd);
    xsplit<<<dim3(NT32, CMID/32, BATCH), dim3(32,8)>>>(ao, aost, CMID,
        (long)CMID*NTOK, (long)NPAD*3*CMID, mean, istd, g2, b2);
    gemm_hmma<<<dim3(NT, 8, BATCH), blk>>>(w3st, aost, y3, 3*CMID,
        (long)NPAD*3*CMID, (long)COUT*NTOK, nullptr, nullptr, nullptr);

    // BN3 + residual + ReLU
    bn_stats<<<COUT, 256>>>(y3, COUT, mean, istd);
    bn_res_relu<<<(BATCH*COUT*NTOK)/256, 256>>>(y3, x, out, mean, istd, g3, b3);
}